// round 12
// baseline (speedup 1.0000x reference)
#include <cuda_runtime.h>
#include <cuda_fp16.h>
#include <math.h>
#include <stdint.h>

#define B 64
#define S 512
#define H 1024
#define E 10
#define G4 4096
#define LSTM_IN 1035

// output packing offsets (flattened pytree order)
#define OFF_FIN 0
#define OFF_H   64
#define OFF_C   (64 + B*H)
#define OFF_A   (64 + 2*B*H)
#define OFF_S   (64 + 2*B*H + B*S)

// attn tiling: block 128(bs) x 128(g), BK=64 stages (2 k-tiles), frag-major
#define BM 128
#define BN 128
#define TILE_B 8192                 // one 128x32 fp16 tile, fragment-major
#define STG (4 * TILE_B)            // A 2 tiles + B 2 tiles = 32768 B
#define NST 3
#define NIT2 16                     // H / 64
#define R_DP (NST * STG)            // 98304
#define R_WV (R_DP + 512)
#define ATTN_SMEM (R_WV + 512)      // 99328 B -> 2 CTAs/SM

#define PADK 36                     // fp32 pad for k_tc64
#define KCH 256                     // split-K chunk for k_tc64

// scratch (no allocation allowed)
__device__ float g_dec_proj[B*H];
__device__ float g_scores[B*S];
__device__ float g_context[B*H];
__device__ float g_gates[B*G4];
__device__ float g_sim[B*E];
__device__ __half g_enc_h[B*S*H];    // fragment-major fp16 mirror of enc
__device__ __half g_wenc_h[H*H];     // fragment-major fp16 mirror of W_enc

__device__ __forceinline__ float sigmoidf_(float x) { return 1.f / (1.f + expf(-x)); }

__device__ __forceinline__ uint32_t smem_u32(const void* p) {
    uint32_t a;
    asm("{ .reg .u64 t; cvta.to.shared.u64 t, %1; cvt.u32.u64 %0, t; }" : "=r"(a) : "l"(p));
    return a;
}

__device__ __forceinline__ uint32_t f2tf32(float x) {   // round-to-nearest tf32
    uint32_t r;
    asm("cvt.rna.tf32.f32 %0, %1;" : "=r"(r) : "f"(x));
    return r;
}

__device__ __forceinline__ uint32_t h2u(float x, float y) {
    __half2 h = __floats2half2_rn(x, y);
    return *reinterpret_cast<uint32_t*>(&h);
}

__device__ __forceinline__ void cp_async16(uint32_t dst, const void* src) {
    asm volatile("cp.async.cg.shared.global [%0], [%1], 16;" :: "r"(dst), "l"(src));
}
#define CP_COMMIT() asm volatile("cp.async.commit_group;" ::: "memory")

__device__ __forceinline__ void mma_f16(float c[4], const uint32_t a[4], const uint32_t b[2]) {
    asm volatile(
        "mma.sync.aligned.m16n8k16.row.col.f32.f16.f16.f32 "
        "{%0,%1,%2,%3}, {%4,%5,%6,%7}, {%8,%9}, {%0,%1,%2,%3};\n"
        : "+f"(c[0]), "+f"(c[1]), "+f"(c[2]), "+f"(c[3])
        : "r"(a[0]), "r"(a[1]), "r"(a[2]), "r"(a[3]), "r"(b[0]), "r"(b[1]));
}

__device__ __forceinline__ void mma_tf32(float c[4], const uint32_t a[4], const uint32_t b[2]) {
    asm volatile(
        "mma.sync.aligned.m16n8k8.row.col.f32.tf32.tf32.f32 "
        "{%0,%1,%2,%3}, {%4,%5,%6,%7}, {%8,%9}, {%0,%1,%2,%3};\n"
        : "+f"(c[0]), "+f"(c[1]), "+f"(c[2]), "+f"(c[3])
        : "r"(a[0]), "r"(a[1]), "r"(a[2]), "r"(a[3]), "r"(b[0]), "r"(b[1]));
}

// ---------------------------------------------------------------------------
// Launch 1: fragment-major fp16 mirror of enc + zero accumulators.
// One thread per 16B A-fragment.  grid = B*S*H*2/16/256 = 16384.
// Tile (rb,kb) at byte offset (rb*32+kb)*8192; in-tile frag (k16*8+m16)*512 + lane*16.
// Lane l (g=l>>2, t=l&3): o.x=(r,2t..2t+1), o.y=(r+8,..), o.z=(r,2t+8..), o.w=(r+8,2t+8..)
// r = rb*128 + m16*16 + g, kcol = kb*32 + k16*16 + 2t.
// ---------------------------------------------------------------------------
__global__ void k_prep1(const float* __restrict__ enc) {
    int i = blockIdx.x * blockDim.x + threadIdx.x;
    int lane = i & 31;
    int sub  = (i >> 5) & 15;
    int k16  = sub >> 3, m16 = sub & 7;
    int tile = i >> 9;
    int kb   = tile & 31, rb = tile >> 5;
    int g = lane >> 2, t = lane & 3;
    int row = rb * 128 + m16 * 16 + g;
    int kcol = kb * 32 + k16 * 16 + 2 * t;

    const float2* e = (const float2*)enc;
    float2 v0 = e[((size_t)row       * H + kcol    ) >> 1];
    float2 v1 = e[((size_t)(row + 8) * H + kcol    ) >> 1];
    float2 v2 = e[((size_t)row       * H + kcol + 8) >> 1];
    float2 v3 = e[((size_t)(row + 8) * H + kcol + 8) >> 1];
    uint4 o;
    o.x = h2u(v0.x, v0.y);
    o.y = h2u(v1.x, v1.y);
    o.z = h2u(v2.x, v2.y);
    o.w = h2u(v3.x, v3.y);
    ((uint4*)g_enc_h)[i] = o;

    if (i < B*S) g_scores[i] = 0.f;
    if (i < B*H) { g_dec_proj[i] = 0.f; g_context[i] = 0.f; }
}

// ---------------------------------------------------------------------------
// Launch 2: fragment-major fp16 mirror of W_enc (8B B-fragments).
// ---------------------------------------------------------------------------
__global__ void k_cvt_w(const float* __restrict__ wenc) {
    int i = blockIdx.x * blockDim.x + threadIdx.x;
    int lane = i & 31;
    int sub  = (i >> 5) & 31;
    int k16  = sub >> 4, n8 = sub & 15;
    int tile = i >> 10;
    int kb   = tile & 31, gb = tile >> 5;
    int g = lane >> 2, t = lane & 3;
    int n = gb * 128 + n8 * 8 + g;
    int k = kb * 32 + k16 * 16 + 2 * t;

    const float2* w = (const float2*)wenc;
    float2 u0 = w[((size_t)n * H + k    ) >> 1];
    float2 u1 = w[((size_t)n * H + k + 8) >> 1];
    uint2 o;
    o.x = h2u(u0.x, u0.y);
    o.y = h2u(u1.x, u1.y);
    ((uint2*)g_wenc_h)[i] = o;
}

// ---------------------------------------------------------------------------
// fp16 fused attention-score GEMM, fragment-major stages, BK=64 per barrier.
// Block tile 128 x 128, 8 warps as 2M x 4N (warp tile 64x32). 2 CTAs/SM.
// 3 stages of 32KB (2 k-tiles each); 16 iterations; 1 barrier per iter.
// grid = (H/BN = 8 [g fastest, L2 reuse], B*S/BM = 256)
// ---------------------------------------------------------------------------
__global__ void __launch_bounds__(256, 2) k_attn_f16(
    const __half* __restrict__ ench,
    const __half* __restrict__ wench,
    const float* __restrict__ w_val)
{
    extern __shared__ char smem[];
    const uint32_t sb = smem_u32(smem);
    const int tid = threadIdx.x;
    const int lane = tid & 31, warp = tid >> 5;
    const int warpM = warp & 1, warpN = warp >> 1;
    const int group = lane >> 2, tid4 = lane & 3;

    const int gb = blockIdx.x;
    const int rb = blockIdx.y;
    const int gBase   = gb * BN;
    const int rowBase = rb * BM;
    const int b = rowBase / S;

    float* dp_s = (float*)(smem + R_DP);
    float* wv_s = (float*)(smem + R_WV);
    if (tid < BN) {
        dp_s[tid] = g_dec_proj[b*H + gBase + tid];
        wv_s[tid] = w_val[gBase + tid];
    }

    const char* Asrc = (const char*)ench  + (size_t)rb * 32 * TILE_B;
    const char* Bsrc = (const char*)wench + (size_t)gb * 32 * TILE_B;

    auto issue = [&](int it, int stg) {
        uint32_t sa = sb + stg * STG;
        const char* a    = Asrc + (size_t)it * (2 * TILE_B);
        const char* bsrc = Bsrc + (size_t)it * (2 * TILE_B);
#pragma unroll
        for (int i = 0; i < 4; i++) {
            int c = (tid + 256 * i) * 16;
            cp_async16(sa + c, a + c);
        }
#pragma unroll
        for (int i = 0; i < 4; i++) {
            int c = (tid + 256 * i) * 16;
            cp_async16(sa + 2*TILE_B + c, bsrc + c);
        }
        CP_COMMIT();
    };

    float acc[4][4][4];
#pragma unroll
    for (int mi = 0; mi < 4; mi++)
#pragma unroll
        for (int ni = 0; ni < 4; ni++)
#pragma unroll
            for (int q = 0; q < 4; q++) acc[mi][ni][q] = 0.f;

    issue(0, 0);
    issue(1, 1);

    for (int it = 0; it < NIT2; it++) {
        if (it < NIT2 - 1) { asm volatile("cp.async.wait_group 1;" ::: "memory"); }
        else               { asm volatile("cp.async.wait_group 0;" ::: "memory"); }
        __syncthreads();
        if (it + 2 < NIT2) issue(it + 2, (it + 2) % NST);

        const char* stg = smem + (it % NST) * STG;

#pragma unroll
        for (int half = 0; half < 2; half++) {
            const char* sA = stg + half * TILE_B;
            const char* sB = stg + 2*TILE_B + half * TILE_B;
#pragma unroll
            for (int k16 = 0; k16 < 2; k16++) {
                uint4 afr[4];
                uint2 bfr[4];
#pragma unroll
                for (int mi = 0; mi < 4; mi++)
                    afr[mi] = *(const uint4*)(sA +
                        ((k16*8 + warpM*4 + mi) * 32 + lane) * 16);
#pragma unroll
                for (int ni = 0; ni < 4; ni++)
                    bfr[ni] = *(const uint2*)(sB +
                        ((k16*16 + warpN*4 + ni) * 32 + lane) * 8);
#pragma unroll
                for (int mi = 0; mi < 4; mi++)
#pragma unroll
                    for (int ni = 0; ni < 4; ni++)
                        mma_f16(acc[mi][ni],
                                reinterpret_cast<const uint32_t*>(&afr[mi]),
                                reinterpret_cast<const uint32_t*>(&bfr[ni]));
            }
        }
    }

    __syncthreads();

    // epilogue: tanh + w_val dot over warp's 32 g-cols, quad shfl reduce, atomic
#pragma unroll
    for (int mi = 0; mi < 4; mi++) {
        float p0 = 0.f, p1 = 0.f;
#pragma unroll
        for (int ni = 0; ni < 4; ni++)
#pragma unroll
            for (int q = 0; q < 2; q++) {
                int g = warpN*32 + ni*8 + 2*tid4 + q;
                float wv = wv_s[g], dp = dp_s[g];
                p0 += wv * tanhf(acc[mi][ni][q    ] + dp);
                p1 += wv * tanhf(acc[mi][ni][2 + q] + dp);
            }
        p0 += __shfl_down_sync(0xffffffffu, p0, 2, 4);
        p0 += __shfl_down_sync(0xffffffffu, p0, 1, 4);
        p1 += __shfl_down_sync(0xffffffffu, p1, 2, 4);
        p1 += __shfl_down_sync(0xffffffffu, p1, 1, 4);
        if (tid4 == 0) {
            int row = rowBase + warpM*64 + mi*16 + group;
            atomicAdd(&g_scores[row    ], p0);
            atomicAdd(&g_scores[row + 8], p1);
        }
    }
}

// ---------------------------------------------------------------------------
// Split-K 64-row GEMM on tensor cores (tf32, RN operands), atomic epilogue.
// ---------------------------------------------------------------------------
__global__ void __launch_bounds__(256) k_tc64(
    const float* __restrict__ A0, const float* __restrict__ W0, int ldw0,
    const float* __restrict__ A1, const float* __restrict__ W1, int ldw1,
    float* __restrict__ C, int ldc)
{
    __shared__ float As[64 * PADK];
    __shared__ float Ws[128 * PADK];
    const int tid = threadIdx.x;
    const int lane = tid & 31, warp = tid >> 5;
    const int warpM = warp & 1, warpN = warp >> 1;
    const int group = lane >> 2, tid4 = lane & 3;
    const int nBase = blockIdx.x * 128;
    const int chunk = blockIdx.y;

    const float* A = (chunk >= 4) ? A1 : A0;
    const float* W = (chunk >= 4) ? W1 : W0;
    const int ldw  = (chunk >= 4) ? ldw1 : ldw0;
    const int kb = (chunk & 3) * KCH;

    float acc[2][4][4];
#pragma unroll
    for (int mi = 0; mi < 2; mi++)
#pragma unroll
        for (int ni = 0; ni < 4; ni++)
#pragma unroll
            for (int q = 0; q < 4; q++) acc[mi][ni][q] = 0.f;

    for (int k0 = kb; k0 < kb + KCH; k0 += 32) {
#pragma unroll
        for (int i = 0; i < 8; i++) {
            int e = tid + 256 * i;
            As[(e >> 5) * PADK + (e & 31)] =
                __uint_as_float(f2tf32(A[(size_t)(e >> 5) * H + k0 + (e & 31)]));
        }
#pragma unroll
        for (int i = 0; i < 16; i++) {
            int e = tid + 256 * i;
            Ws[(e >> 5) * PADK + (e & 31)] =
                __uint_as_float(f2tf32(W[(size_t)(nBase + (e >> 5)) * ldw + k0 + (e & 31)]));
        }
        __syncthreads();
#pragma unroll
        for (int k8 = 0; k8 < 4; k8++) {
            int kk = k8 * 8;
            uint32_t afr[2][4], bfr[4][2];
#pragma unroll
            for (int mi = 0; mi < 2; mi++) {
                int m = warpM*32 + mi*16 + group;
                afr[mi][0] = __float_as_uint(As[(m    )*PADK + kk + tid4    ]);
                afr[mi][1] = __float_as_uint(As[(m + 8)*PADK + kk + tid4    ]);
                afr[mi][2] = __float_as_uint(As[(m    )*PADK + kk + tid4 + 4]);
                afr[mi][3] = __float_as_uint(As[(m + 8)*PADK + kk + tid4 + 4]);
            }
#pragma unroll
            for (int ni = 0; ni < 4; ni++) {
                int n = warpN*32 + ni*8 + group;
                bfr[ni][0] = __float_as_uint(Ws[n*PADK + kk + tid4    ]);
                bfr[ni][1] = __float_as_uint(Ws[n*PADK + kk + tid4 + 4]);
            }
#pragma unroll
            for (int mi = 0; mi < 2; mi++)
#pragma unroll
                for (int ni = 0; ni < 4; ni++)
                    mma_tf32(acc[mi][ni], afr[mi], bfr[ni]);
        }
        __syncthreads();
    }

#pragma unroll
    for (int mi = 0; mi < 2; mi++)
#pragma unroll
        for (int ni = 0; ni < 4; ni++) {
            int row = warpM*32 + mi*16 + group;
            int col = nBase + warpN*32 + ni*8 + 2*tid4;
            atomicAdd(&C[(size_t)row*ldc + col],         acc[mi][ni][0]);
            atomicAdd(&C[(size_t)row*ldc + col + 1],     acc[mi][ni][1]);
            atomicAdd(&C[(size_t)(row+8)*ldc + col],     acc[mi][ni][2]);
            atomicAdd(&C[(size_t)(row+8)*ldc + col + 1], acc[mi][ni][3]);
        }
}

// ---------------------------------------------------------------------------
__global__ void k_softmax(float* __restrict__ out)
{
    int b = blockIdx.x, tid = threadIdx.x;
    __shared__ float red[256];
    float s0 = g_scores[b*S + tid];
    float s1 = g_scores[b*S + 256 + tid];
    red[tid] = fmaxf(s0, s1);
    __syncthreads();
    for (int off = 128; off > 0; off >>= 1) {
        if (tid < off) red[tid] = fmaxf(red[tid], red[tid + off]);
        __syncthreads();
    }
    float m = red[0];
    __syncthreads();
    float e0 = expf(s0 - m), e1 = expf(s1 - m);
    red[tid] = e0 + e1;
    __syncthreads();
    for (int off = 128; off > 0; off >>= 1) {
        if (tid < off) red[tid] += red[tid + off];
        __syncthreads();
    }
    float inv = 1.f / red[0];
    out[OFF_A + b*S + tid]       = e0 * inv;
    out[OFF_A + b*S + 256 + tid] = e1 * inv;
}

// ---------------------------------------------------------------------------
// context from fragment-major fp16 mirror.  grid = 256 (rb tiles), block 256.
// Per tile: warps read 512B fragment sets, weight by attn, g-shuffle reduce,
// smem ctx accumulate, then one global atomic pass.
// ---------------------------------------------------------------------------
__global__ void __launch_bounds__(256) k_ctx(
    const __half* __restrict__ ench, const float* __restrict__ out)
{
    __shared__ float w[128];
    __shared__ float ctx[H];
    const int rb = blockIdx.x;
    const int b = rb >> 2;
    const int tid = threadIdx.x;
    const int warp = tid >> 5, lane = tid & 31;
    const int g = lane >> 2, t = lane & 3;

    if (tid < 128) w[tid] = out[OFF_A + b*S + (rb & 3)*128 + tid];
    for (int j = tid; j < H; j += 256) ctx[j] = 0.f;
    __syncthreads();

    const uint4* base = (const uint4*)((const char*)ench + (size_t)rb * 32 * TILE_B);

    for (int kb = 0; kb < 32; kb++) {
#pragma unroll
        for (int i = 0; i < 2; i++) {
            int set = warp * 2 + i;          // 0..15
            int k16 = set >> 3, m16 = set & 7;
            uint4 o = base[kb * 512 + (k16*8 + m16) * 32 + lane];
            float2 x0 = __half22float2(*reinterpret_cast<__half2*>(&o.x));
            float2 x1 = __half22float2(*reinterpret_cast<__half2*>(&o.y));
            float2 x2 = __half22float2(*reinterpret_cast<__half2*>(&o.z));
            float2 x3 = __half22float2(*reinterpret_cast<__half2*>(&o.w));
            int r0 = m16*16 + g;
            float w0 = w[r0], w1 = w[r0 + 8];
            float c0 = w0*x0.x + w1*x1.x;
            float c1 = w0*x0.y + w1*x1.y;
            float c2 = w0*x2.x + w1*x3.x;
            float c3 = w0*x2.y + w1*x3.y;
#pragma unroll
            for (int off = 16; off >= 4; off >>= 1) {
                c0 += __shfl_down_sync(0xffffffffu, c0, off);
                c1 += __shfl_down_sync(0xffffffffu, c1, off);
                c2 += __shfl_down_sync(0xffffffffu, c2, off);
                c3 += __shfl_down_sync(0xffffffffu, c3, off);
            }
            if (lane < 4) {
                int k = kb*32 + k16*16 + 2*t;
                atomicAdd(&ctx[k    ], c0);
                atomicAdd(&ctx[k + 1], c1);
                atomicAdd(&ctx[k + 8], c2);
                atomicAdd(&ctx[k + 9], c3);
            }
        }
    }
    __syncthreads();
    for (int j = tid; j < H; j += 256)
        atomicAdd(&g_context[b*H + j], ctx[j]);
}

// ---------------------------------------------------------------------------
__global__ void k_sim(const float* __restrict__ events,
                      const float* __restrict__ W_gate,
                      float* __restrict__ out)
{
    int b = blockIdx.x;
    int tid = threadIdx.x, warp = tid >> 5, lane = tid & 31;
    __shared__ float t[E];
    if (warp < E) {
        float acc = 0.f;
        for (int h = lane; h < H; h += 32)
            acc += g_context[b*H + h] * events[warp*H + h];
#pragma unroll
        for (int off = 16; off > 0; off >>= 1)
            acc += __shfl_down_sync(0xffffffffu, acc, off);
        if (lane == 0) t[warp] = acc;
    }
    __syncthreads();
    if (tid < E) {
        float s = 0.f;
#pragma unroll
        for (int e = 0; e < E; e++) s += t[e] * W_gate[tid*E + e];
        g_sim[b*E + tid] = s;
        out[OFF_S + b*E + tid] = s;
    }
}

// ---------------------------------------------------------------------------
__global__ void k_gates_init(const float* __restrict__ x,
                             const float* __restrict__ W_ih,
                             const float* __restrict__ b_ih,
                             const float* __restrict__ b_hh)
{
    int b = blockIdx.x;
    int j = blockIdx.y * 256 + threadIdx.x;
    const float* wr = W_ih + (size_t)j * LSTM_IN;
    float v = b_ih[j] + b_hh[j] + x[b] * wr[1034];
#pragma unroll
    for (int e = 0; e < E; e++) v += g_sim[b*E + e] * wr[1024 + e];
    g_gates[b*G4 + j] = v;
}

// ---------------------------------------------------------------------------
__global__ void k_lstm_final(const float* __restrict__ c0,
                             const float* __restrict__ ln_g,
                             const float* __restrict__ ln_b,
                             const float* __restrict__ W_fin,
                             const float* __restrict__ b_fin,
                             float* __restrict__ out)
{
    int b = blockIdx.x, tid = threadIdx.x;
    __shared__ float red[256];
    float hv[4];
    float sum = 0.f;
#pragma unroll
    for (int r = 0; r < 4; r++) {
        int h = r*256 + tid;
        float ig = g_gates[b*G4 + h];
        float fg = g_gates[b*G4 + 1024 + h];
        float gg = g_gates[b*G4 + 2048 + h];
        float og = g_gates[b*G4 + 3072 + h];
        float cn = sigmoidf_(fg) * c0[b*H + h] + sigmoidf_(ig) * tanhf(gg);
        float hn = sigmoidf_(og) * tanhf(cn);
        out[OFF_H + b*H + h] = hn;
        out[OFF_C + b*H + h] = cn;
        hv[r] = hn;
        sum += hn;
    }
    red[tid] = sum; __syncthreads();
    for (int off = 128; off > 0; off >>= 1) {
        if (tid < off) red[tid] += red[tid + off];
        __syncthreads();
    }
    float mu = red[0] * (1.f / H);
    __syncthreads();
    float sq = 0.f;
#pragma unroll
    for (int r = 0; r < 4; r++) { float d = hv[r] - mu; sq += d * d; }
    red[tid] = sq; __syncthreads();
    for (int off = 128; off > 0; off >>= 1) {
        if (tid < off) red[tid] += red[tid + off];
        __syncthreads();
    }
    float rstd = rsqrtf(red[0] * (1.f / H) + 1e-5f);
    __syncthreads();
    float fp = 0.f;
#pragma unroll
    for (int r = 0; r < 4; r++) {
        int h = r*256 + tid;
        float y = (hv[r] - mu) * rstd * ln_g[h] + ln_b[h];
        fp += y * W_fin[h];
    }
    red[tid] = fp; __syncthreads();
    for (int off = 128; off > 0; off >>= 1) {
        if (tid < off) red[tid] += red[tid + off];
        __syncthreads();
    }
    if (tid == 0) out[OFF_FIN + b] = red[0] + b_fin[0];
}

// ---------------------------------------------------------------------------
extern "C" void kernel_launch(void* const* d_in, const int* in_sizes, int n_in,
                              void* d_out, int out_size)
{
    const float* x      = (const float*)d_in[0];
    const float* h0     = (const float*)d_in[1];
    const float* c0     = (const float*)d_in[2];
    const float* enc    = (const float*)d_in[3];
    const float* W_enc  = (const float*)d_in[4];
    const float* W_dec  = (const float*)d_in[5];
    const float* w_val  = (const float*)d_in[6];
    const float* W_gate = (const float*)d_in[7];
    const float* events = (const float*)d_in[8];
    const float* W_ih   = (const float*)d_in[9];
    const float* W_hh   = (const float*)d_in[10];
    const float* b_ih   = (const float*)d_in[11];
    const float* b_hh   = (const float*)d_in[12];
    const float* ln_g   = (const float*)d_in[13];
    const float* ln_b   = (const float*)d_in[14];
    const float* W_fin  = (const float*)d_in[15];
    const float* b_fin  = (const float*)d_in[16];
    float* out = (float*)d_out;

    void* p;
    cudaGetSymbolAddress(&p, g_dec_proj); float*  dec_proj = (float*)p;
    cudaGetSymbolAddress(&p, g_context);  float*  context  = (float*)p;
    cudaGetSymbolAddress(&p, g_gates);    float*  gates    = (float*)p;
    cudaGetSymbolAddress(&p, g_enc_h);    __half* ench     = (__half*)p;
    cudaGetSymbolAddress(&p, g_wenc_h);   __half* wench    = (__half*)p;

    cudaFuncSetAttribute(k_attn_f16, cudaFuncAttributeMaxDynamicSharedMemorySize, ATTN_SMEM);

    // launch 1: fragment-major enc mirror + zeroing
    k_prep1<<<B*S*H*2/16/256, 256>>>(enc);
    // launch 2: fragment-major W_enc mirror
    k_cvt_w<<<H*H*2/8/256, 256>>>(W_enc);
    // launch 3: dec_proj = h0 @ W_dec^T (tf32, split-K)
    k_tc64<<<dim3(H / 128, 4), 256>>>(h0, W_dec, H, nullptr, nullptr, 0, dec_proj, H);
    // launch 4: fused scores (ncu profiles this one)
    k_attn_f16<<<dim3(H / BN, B * S / BM), 256, ATTN_SMEM>>>(ench, wench, w_val);

    k_softmax<<<B, 256>>>(out);
    k_ctx<<<B * S / BM, 256>>>(ench, out);
    k_sim<<<B, 320>>>(events, W_gate, out);
    k_gates_init<<<dim3(B, 16), 256>>>(x, W_ih, b_ih, b_hh);

    // gates += context @ W_ih[:, :1024]^T + h0 @ W_hh^T (split-K, 256 CTAs)
    k_tc64<<<dim3(G4 / 128, 8), 256>>>(context, W_ih, LSTM_IN, h0, W_hh, H, gates, G4);

    k_lstm_final<<<B, 256>>>(c0, ln_g, ln_b, W_fin, b_fin, out);
}

// round 13
// speedup vs baseline: 1.4802x; 1.4802x over previous
#include <cuda_runtime.h>
#include <cuda_fp16.h>
#include <math.h>
#include <stdint.h>

#define B 64
#define S 512
#define H 1024
#define E 10
#define G4 4096
#define LSTM_IN 1035

// output packing offsets (flattened pytree order)
#define OFF_FIN 0
#define OFF_H   64
#define OFF_C   (64 + B*H)
#define OFF_A   (64 + 2*B*H)
#define OFF_S   (64 + 2*B*H + B*S)

// attn tiling: block 128(bs) x 128(g), BK=32, fragment-major smem stages (R11 proven)
#define BM 128
#define BN 128
#define BK 32
#define NITER (H / BK)            // 32
#define TILE_B 8192                // one 128x32 fp16 tile, fragment-major
#define STG (2 * TILE_B)           // A tile + B tile = 16384 B
#define NST 4
#define R_DP (NST * STG)           // 65536
#define R_WV (R_DP + 512)
#define ATTN_SMEM (R_WV + 512)     // 66560 B -> 2 CTAs/SM

#define PADK 36                    // fp32 pad for k_tc64
#define KCH 128                    // split-K chunk for k_tc64 (8 chunks per source)

// scratch (no allocation allowed)
__device__ float g_dec_proj[B*H];
__device__ float g_scores[B*S];
__device__ float g_context[B*H];
__device__ float g_gates[B*G4];
__device__ float g_sim[B*E];
__device__ __half g_enc_h[B*S*H];    // fragment-major fp16 mirror of enc
__device__ __half g_wenc_h[H*H];     // fragment-major fp16 mirror of W_enc

__device__ __forceinline__ float sigmoidf_(float x) { return 1.f / (1.f + expf(-x)); }

__device__ __forceinline__ uint32_t smem_u32(const void* p) {
    uint32_t a;
    asm("{ .reg .u64 t; cvta.to.shared.u64 t, %1; cvt.u32.u64 %0, t; }" : "=r"(a) : "l"(p));
    return a;
}

__device__ __forceinline__ uint32_t f2tf32(float x) {   // round-to-nearest tf32
    uint32_t r;
    asm("cvt.rna.tf32.f32 %0, %1;" : "=r"(r) : "f"(x));
    return r;
}

__device__ __forceinline__ uint32_t h2u(float x, float y) {
    __half2 h = __floats2half2_rn(x, y);
    return *reinterpret_cast<uint32_t*>(&h);
}

__device__ __forceinline__ void cp_async16(uint32_t dst, const void* src) {
    asm volatile("cp.async.cg.shared.global [%0], [%1], 16;" :: "r"(dst), "l"(src));
}
#define CP_COMMIT() asm volatile("cp.async.commit_group;" ::: "memory")

__device__ __forceinline__ void mma_f16(float c[4], const uint32_t a[4], const uint32_t b[2]) {
    asm volatile(
        "mma.sync.aligned.m16n8k16.row.col.f32.f16.f16.f32 "
        "{%0,%1,%2,%3}, {%4,%5,%6,%7}, {%8,%9}, {%0,%1,%2,%3};\n"
        : "+f"(c[0]), "+f"(c[1]), "+f"(c[2]), "+f"(c[3])
        : "r"(a[0]), "r"(a[1]), "r"(a[2]), "r"(a[3]), "r"(b[0]), "r"(b[1]));
}

__device__ __forceinline__ void mma_tf32(float c[4], const uint32_t a[4], const uint32_t b[2]) {
    asm volatile(
        "mma.sync.aligned.m16n8k8.row.col.f32.tf32.tf32.f32 "
        "{%0,%1,%2,%3}, {%4,%5,%6,%7}, {%8,%9}, {%0,%1,%2,%3};\n"
        : "+f"(c[0]), "+f"(c[1]), "+f"(c[2]), "+f"(c[3])
        : "r"(a[0]), "r"(a[1]), "r"(a[2]), "r"(a[3]), "r"(b[0]), "r"(b[1]));
}

// ---------------------------------------------------------------------------
// Launch 1: fragment-major fp16 mirror of enc + zero accumulators.
// One thread per 16B A-fragment.  grid = B*S*H*2/16/256 = 16384.
// Tile (rb,kb) at byte offset (rb*32+kb)*8192; in-tile frag (k16*8+m16)*512 + lane*16.
// Lane l (g=l>>2, t=l&3): o.x=(r,2t..2t+1), o.y=(r+8,..), o.z=(r,2t+8..), o.w=(r+8,2t+8..)
// r = rb*128 + m16*16 + g, kcol = kb*32 + k16*16 + 2t.
// ---------------------------------------------------------------------------
__global__ void k_prep1(const float* __restrict__ enc) {
    int i = blockIdx.x * blockDim.x + threadIdx.x;
    int lane = i & 31;
    int sub  = (i >> 5) & 15;
    int k16  = sub >> 3, m16 = sub & 7;
    int tile = i >> 9;
    int kb   = tile & 31, rb = tile >> 5;
    int g = lane >> 2, t = lane & 3;
    int row = rb * 128 + m16 * 16 + g;
    int kcol = kb * 32 + k16 * 16 + 2 * t;

    const float2* e = (const float2*)enc;
    float2 v0 = e[((size_t)row       * H + kcol    ) >> 1];
    float2 v1 = e[((size_t)(row + 8) * H + kcol    ) >> 1];
    float2 v2 = e[((size_t)row       * H + kcol + 8) >> 1];
    float2 v3 = e[((size_t)(row + 8) * H + kcol + 8) >> 1];
    uint4 o;
    o.x = h2u(v0.x, v0.y);
    o.y = h2u(v1.x, v1.y);
    o.z = h2u(v2.x, v2.y);
    o.w = h2u(v3.x, v3.y);
    ((uint4*)g_enc_h)[i] = o;

    if (i < B*S) g_scores[i] = 0.f;
    if (i < B*H) g_dec_proj[i] = 0.f;
}

// ---------------------------------------------------------------------------
// Launch 2: fragment-major fp16 mirror of W_enc (8B B-fragments).
// ---------------------------------------------------------------------------
__global__ void k_cvt_w(const float* __restrict__ wenc) {
    int i = blockIdx.x * blockDim.x + threadIdx.x;
    int lane = i & 31;
    int sub  = (i >> 5) & 31;
    int k16  = sub >> 4, n8 = sub & 15;
    int tile = i >> 10;
    int kb   = tile & 31, gb = tile >> 5;
    int g = lane >> 2, t = lane & 3;
    int n = gb * 128 + n8 * 8 + g;
    int k = kb * 32 + k16 * 16 + 2 * t;

    const float2* w = (const float2*)wenc;
    float2 u0 = w[((size_t)n * H + k    ) >> 1];
    float2 u1 = w[((size_t)n * H + k + 8) >> 1];
    uint2 o;
    o.x = h2u(u0.x, u0.y);
    o.y = h2u(u1.x, u1.y);
    ((uint2*)g_wenc_h)[i] = o;
}

// ---------------------------------------------------------------------------
// fp16 fused attention-score GEMM, fragment-major stages (R11 proven).
// Block tile 128 x 128, 8 warps as 2M x 4N (warp tile 64x32). 2 CTAs/SM.
// 4 stages, prefetch depth 3, ONE barrier per iter.
// grid = (H/BN = 8 [g fastest, L2 reuse], B*S/BM = 256)
// ---------------------------------------------------------------------------
__global__ void __launch_bounds__(256, 2) k_attn_f16(
    const __half* __restrict__ ench,
    const __half* __restrict__ wench,
    const float* __restrict__ w_val)
{
    extern __shared__ char smem[];
    const uint32_t sb = smem_u32(smem);
    const int tid = threadIdx.x;
    const int lane = tid & 31, warp = tid >> 5;
    const int warpM = warp & 1, warpN = warp >> 1;
    const int group = lane >> 2, tid4 = lane & 3;

    const int gb = blockIdx.x;
    const int rb = blockIdx.y;
    const int gBase   = gb * BN;
    const int rowBase = rb * BM;
    const int b = rowBase / S;

    float* dp_s = (float*)(smem + R_DP);
    float* wv_s = (float*)(smem + R_WV);
    if (tid < BN) {
        dp_s[tid] = g_dec_proj[b*H + gBase + tid];
        wv_s[tid] = w_val[gBase + tid];
    }

    const char* Asrc = (const char*)ench  + (size_t)rb * 32 * TILE_B;
    const char* Bsrc = (const char*)wench + (size_t)gb * 32 * TILE_B;

    auto issue = [&](int it, int stg) {
        uint32_t sa = sb + stg * STG;
        const char* a = Asrc + (size_t)it * TILE_B;
        const char* bsrc = Bsrc + (size_t)it * TILE_B;
#pragma unroll
        for (int i = 0; i < 2; i++) {
            int c = (tid + 256 * i) * 16;
            cp_async16(sa + c, a + c);
        }
#pragma unroll
        for (int i = 0; i < 2; i++) {
            int c = (tid + 256 * i) * 16;
            cp_async16(sa + TILE_B + c, bsrc + c);
        }
        CP_COMMIT();
    };

    float acc[4][4][4];
#pragma unroll
    for (int mi = 0; mi < 4; mi++)
#pragma unroll
        for (int ni = 0; ni < 4; ni++)
#pragma unroll
            for (int q = 0; q < 4; q++) acc[mi][ni][q] = 0.f;

    issue(0, 0);
    issue(1, 1);
    issue(2, 2);

    for (int it = 0; it < NITER; it++) {
        if (it <= NITER - 3)      { asm volatile("cp.async.wait_group 2;" ::: "memory"); }
        else if (it == NITER - 2) { asm volatile("cp.async.wait_group 1;" ::: "memory"); }
        else                      { asm volatile("cp.async.wait_group 0;" ::: "memory"); }
        __syncthreads();
        if (it + 3 < NITER) issue(it + 3, (it + 3) & 3);

        const char* stg = smem + (it & 3) * STG;

#pragma unroll
        for (int k16 = 0; k16 < 2; k16++) {
            uint4 afr[4];
            uint2 bfr[4];
#pragma unroll
            for (int mi = 0; mi < 4; mi++)
                afr[mi] = *(const uint4*)(stg +
                    ((k16*8 + warpM*4 + mi) * 32 + lane) * 16);
#pragma unroll
            for (int ni = 0; ni < 4; ni++)
                bfr[ni] = *(const uint2*)(stg + TILE_B +
                    ((k16*16 + warpN*4 + ni) * 32 + lane) * 8);
#pragma unroll
            for (int mi = 0; mi < 4; mi++)
#pragma unroll
                for (int ni = 0; ni < 4; ni++)
                    mma_f16(acc[mi][ni],
                            reinterpret_cast<const uint32_t*>(&afr[mi]),
                            reinterpret_cast<const uint32_t*>(&bfr[ni]));
        }
    }

    __syncthreads();

    // epilogue: tanh + w_val dot over warp's 32 g-cols, quad shfl reduce, atomic
#pragma unroll
    for (int mi = 0; mi < 4; mi++) {
        float p0 = 0.f, p1 = 0.f;
#pragma unroll
        for (int ni = 0; ni < 4; ni++)
#pragma unroll
            for (int q = 0; q < 2; q++) {
                int g = warpN*32 + ni*8 + 2*tid4 + q;
                float wv = wv_s[g], dp = dp_s[g];
                p0 += wv * tanhf(acc[mi][ni][q    ] + dp);
                p1 += wv * tanhf(acc[mi][ni][2 + q] + dp);
            }
        p0 += __shfl_down_sync(0xffffffffu, p0, 2, 4);
        p0 += __shfl_down_sync(0xffffffffu, p0, 1, 4);
        p1 += __shfl_down_sync(0xffffffffu, p1, 2, 4);
        p1 += __shfl_down_sync(0xffffffffu, p1, 1, 4);
        if (tid4 == 0) {
            int row = rowBase + warpM*64 + mi*16 + group;
            atomicAdd(&g_scores[row    ], p0);
            atomicAdd(&g_scores[row + 8], p1);
        }
    }
}

// ---------------------------------------------------------------------------
// Split-K 64-row GEMM on tensor cores (tf32, RN operands), atomic epilogue.
// grid = (N/128, nChunks).  src = chunk>>3 (8 KCH=128 chunks per source),
// kb = (chunk&7)*KCH.
// ---------------------------------------------------------------------------
__global__ void __launch_bounds__(256) k_tc64(
    const float* __restrict__ A0, const float* __restrict__ W0, int ldw0,
    const float* __restrict__ A1, const float* __restrict__ W1, int ldw1,
    float* __restrict__ C, int ldc)
{
    __shared__ float As[64 * PADK];
    __shared__ float Ws[128 * PADK];
    const int tid = threadIdx.x;
    const int lane = tid & 31, warp = tid >> 5;
    const int warpM = warp & 1, warpN = warp >> 1;
    const int group = lane >> 2, tid4 = lane & 3;
    const int nBase = blockIdx.x * 128;
    const int chunk = blockIdx.y;

    const float* A = (chunk >= 8) ? A1 : A0;
    const float* W = (chunk >= 8) ? W1 : W0;
    const int ldw  = (chunk >= 8) ? ldw1 : ldw0;
    const int kb = (chunk & 7) * KCH;

    float acc[2][4][4];
#pragma unroll
    for (int mi = 0; mi < 2; mi++)
#pragma unroll
        for (int ni = 0; ni < 4; ni++)
#pragma unroll
            for (int q = 0; q < 4; q++) acc[mi][ni][q] = 0.f;

    for (int k0 = kb; k0 < kb + KCH; k0 += 32) {
#pragma unroll
        for (int i = 0; i < 8; i++) {
            int e = tid + 256 * i;
            As[(e >> 5) * PADK + (e & 31)] =
                __uint_as_float(f2tf32(A[(size_t)(e >> 5) * H + k0 + (e & 31)]));
        }
#pragma unroll
        for (int i = 0; i < 16; i++) {
            int e = tid + 256 * i;
            Ws[(e >> 5) * PADK + (e & 31)] =
                __uint_as_float(f2tf32(W[(size_t)(nBase + (e >> 5)) * ldw + k0 + (e & 31)]));
        }
        __syncthreads();
#pragma unroll
        for (int k8 = 0; k8 < 4; k8++) {
            int kk = k8 * 8;
            uint32_t afr[2][4], bfr[4][2];
#pragma unroll
            for (int mi = 0; mi < 2; mi++) {
                int m = warpM*32 + mi*16 + group;
                afr[mi][0] = __float_as_uint(As[(m    )*PADK + kk + tid4    ]);
                afr[mi][1] = __float_as_uint(As[(m + 8)*PADK + kk + tid4    ]);
                afr[mi][2] = __float_as_uint(As[(m    )*PADK + kk + tid4 + 4]);
                afr[mi][3] = __float_as_uint(As[(m + 8)*PADK + kk + tid4 + 4]);
            }
#pragma unroll
            for (int ni = 0; ni < 4; ni++) {
                int n = warpN*32 + ni*8 + group;
                bfr[ni][0] = __float_as_uint(Ws[n*PADK + kk + tid4    ]);
                bfr[ni][1] = __float_as_uint(Ws[n*PADK + kk + tid4 + 4]);
            }
#pragma unroll
            for (int mi = 0; mi < 2; mi++)
#pragma unroll
                for (int ni = 0; ni < 4; ni++)
                    mma_tf32(acc[mi][ni], afr[mi], bfr[ni]);
        }
        __syncthreads();
    }

#pragma unroll
    for (int mi = 0; mi < 2; mi++)
#pragma unroll
        for (int ni = 0; ni < 4; ni++) {
            int row = warpM*32 + mi*16 + group;
            int col = nBase + warpN*32 + ni*8 + 2*tid4;
            atomicAdd(&C[(size_t)row*ldc + col],         acc[mi][ni][0]);
            atomicAdd(&C[(size_t)row*ldc + col + 1],     acc[mi][ni][1]);
            atomicAdd(&C[(size_t)(row+8)*ldc + col],     acc[mi][ni][2]);
            atomicAdd(&C[(size_t)(row+8)*ldc + col + 1], acc[mi][ni][3]);
        }
}

// ---------------------------------------------------------------------------
__global__ void k_softmax(float* __restrict__ out)
{
    int b = blockIdx.x, tid = threadIdx.x;
    __shared__ float red[256];
    float s0 = g_scores[b*S + tid];
    float s1 = g_scores[b*S + 256 + tid];
    red[tid] = fmaxf(s0, s1);
    __syncthreads();
    for (int off = 128; off > 0; off >>= 1) {
        if (tid < off) red[tid] = fmaxf(red[tid], red[tid + off]);
        __syncthreads();
    }
    float m = red[0];
    __syncthreads();
    float e0 = expf(s0 - m), e1 = expf(s1 - m);
    red[tid] = e0 + e1;
    __syncthreads();
    for (int off = 128; off > 0; off >>= 1) {
        if (tid < off) red[tid] += red[tid + off];
        __syncthreads();
    }
    float inv = 1.f / red[0];
    out[OFF_A + b*S + tid]       = e0 * inv;
    out[OFF_A + b*S + 256 + tid] = e1 * inv;
}

// ---------------------------------------------------------------------------
// context from fp32 enc (mirror is fragment-major).  grid (B, 4) x 256.
__global__ void k_context(const float* __restrict__ enc, const float* __restrict__ out)
{
    int b = blockIdx.x;
    int h = blockIdx.y * 256 + threadIdx.x;
    __shared__ float w[S];
    for (int s = threadIdx.x; s < S; s += 256) w[s] = out[OFF_A + b*S + s];
    __syncthreads();
    const float* p = enc + (size_t)b * S * H + h;
    float a0 = 0.f, a1 = 0.f, a2 = 0.f, a3 = 0.f;
#pragma unroll 4
    for (int s = 0; s < S; s += 4) {
        a0 += w[s]     * p[(size_t)s * H];
        a1 += w[s + 1] * p[(size_t)(s + 1) * H];
        a2 += w[s + 2] * p[(size_t)(s + 2) * H];
        a3 += w[s + 3] * p[(size_t)(s + 3) * H];
    }
    g_context[b*H + h] = (a0 + a1) + (a2 + a3);
}

// ---------------------------------------------------------------------------
__global__ void k_sim(const float* __restrict__ events,
                      const float* __restrict__ W_gate,
                      float* __restrict__ out)
{
    int b = blockIdx.x;
    int tid = threadIdx.x, warp = tid >> 5, lane = tid & 31;
    __shared__ float t[E];
    if (warp < E) {
        float acc = 0.f;
        for (int h = lane; h < H; h += 32)
            acc += g_context[b*H + h] * events[warp*H + h];
#pragma unroll
        for (int off = 16; off > 0; off >>= 1)
            acc += __shfl_down_sync(0xffffffffu, acc, off);
        if (lane == 0) t[warp] = acc;
    }
    __syncthreads();
    if (tid < E) {
        float s = 0.f;
#pragma unroll
        for (int e = 0; e < E; e++) s += t[e] * W_gate[tid*E + e];
        g_sim[b*E + tid] = s;
        out[OFF_S + b*E + tid] = s;
    }
}

// ---------------------------------------------------------------------------
__global__ void k_gates_init(const float* __restrict__ x,
                             const float* __restrict__ W_ih,
                             const float* __restrict__ b_ih,
                             const float* __restrict__ b_hh)
{
    int b = blockIdx.x;
    int j = blockIdx.y * 256 + threadIdx.x;
    const float* wr = W_ih + (size_t)j * LSTM_IN;
    float v = b_ih[j] + b_hh[j] + x[b] * wr[1034];
#pragma unroll
    for (int e = 0; e < E; e++) v += g_sim[b*E + e] * wr[1024 + e];
    g_gates[b*G4 + j] = v;
}

// ---------------------------------------------------------------------------
__global__ void k_lstm_final(const float* __restrict__ c0,
                             const float* __restrict__ ln_g,
                             const float* __restrict__ ln_b,
                             const float* __restrict__ W_fin,
                             const float* __restrict__ b_fin,
                             float* __restrict__ out)
{
    int b = blockIdx.x, tid = threadIdx.x;
    __shared__ float red[256];
    float hv[4];
    float sum = 0.f;
#pragma unroll
    for (int r = 0; r < 4; r++) {
        int h = r*256 + tid;
        float ig = g_gates[b*G4 + h];
        float fg = g_gates[b*G4 + 1024 + h];
        float gg = g_gates[b*G4 + 2048 + h];
        float og = g_gates[b*G4 + 3072 + h];
        float cn = sigmoidf_(fg) * c0[b*H + h] + sigmoidf_(ig) * tanhf(gg);
        float hn = sigmoidf_(og) * tanhf(cn);
        out[OFF_H + b*H + h] = hn;
        out[OFF_C + b*H + h] = cn;
        hv[r] = hn;
        sum += hn;
    }
    red[tid] = sum; __syncthreads();
    for (int off = 128; off > 0; off >>= 1) {
        if (tid < off) red[tid] += red[tid + off];
        __syncthreads();
    }
    float mu = red[0] * (1.f / H);
    __syncthreads();
    float sq = 0.f;
#pragma unroll
    for (int r = 0; r < 4; r++) { float d = hv[r] - mu; sq += d * d; }
    red[tid] = sq; __syncthreads();
    for (int off = 128; off > 0; off >>= 1) {
        if (tid < off) red[tid] += red[tid + off];
        __syncthreads();
    }
    float rstd = rsqrtf(red[0] * (1.f / H) + 1e-5f);
    __syncthreads();
    float fp = 0.f;
#pragma unroll
    for (int r = 0; r < 4; r++) {
        int h = r*256 + tid;
        float y = (hv[r] - mu) * rstd * ln_g[h] + ln_b[h];
        fp += y * W_fin[h];
    }
    red[tid] = fp; __syncthreads();
    for (int off = 128; off > 0; off >>= 1) {
        if (tid < off) red[tid] += red[tid + off];
        __syncthreads();
    }
    if (tid == 0) out[OFF_FIN + b] = red[0] + b_fin[0];
}

// ---------------------------------------------------------------------------
extern "C" void kernel_launch(void* const* d_in, const int* in_sizes, int n_in,
                              void* d_out, int out_size)
{
    const float* x      = (const float*)d_in[0];
    const float* h0     = (const float*)d_in[1];
    const float* c0     = (const float*)d_in[2];
    const float* enc    = (const float*)d_in[3];
    const float* W_enc  = (const float*)d_in[4];
    const float* W_dec  = (const float*)d_in[5];
    const float* w_val  = (const float*)d_in[6];
    const float* W_gate = (const float*)d_in[7];
    const float* events = (const float*)d_in[8];
    const float* W_ih   = (const float*)d_in[9];
    const float* W_hh   = (const float*)d_in[10];
    const float* b_ih   = (const float*)d_in[11];
    const float* b_hh   = (const float*)d_in[12];
    const float* ln_g   = (const float*)d_in[13];
    const float* ln_b   = (const float*)d_in[14];
    const float* W_fin  = (const float*)d_in[15];
    const float* b_fin  = (const float*)d_in[16];
    float* out = (float*)d_out;

    void* p;
    cudaGetSymbolAddress(&p, g_dec_proj); float*  dec_proj = (float*)p;
    cudaGetSymbolAddress(&p, g_context);  float*  context  = (float*)p;
    cudaGetSymbolAddress(&p, g_gates);    float*  gates    = (float*)p;
    cudaGetSymbolAddress(&p, g_enc_h);    __half* ench     = (__half*)p;
    cudaGetSymbolAddress(&p, g_wenc_h);   __half* wench    = (__half*)p;

    cudaFuncSetAttribute(k_attn_f16, cudaFuncAttributeMaxDynamicSharedMemorySize, ATTN_SMEM);

    // launch 1: fragment-major enc mirror + zeroing
    k_prep1<<<B*S*H*2/16/256, 256>>>(enc);
    // launch 2: fragment-major W_enc mirror
    k_cvt_w<<<H*H*2/8/256, 256>>>(W_enc);
    // launch 3: dec_proj = h0 @ W_dec^T (tf32, split-K 8 chunks, 64 CTAs)
    k_tc64<<<dim3(H / 128, 8), 256>>>(h0, W_dec, H, nullptr, nullptr, 0, dec_proj, H);
    // launch 4: fused scores (ncu profiles this one)
    k_attn_f16<<<dim3(H / BN, B * S / BM), 256, ATTN_SMEM>>>(ench, wench, w_val);

    k_softmax<<<B, 256>>>(out);
    k_context<<<dim3(B, H / 256), 256>>>(enc, out);
    k_sim<<<B, 320>>>(events, W_gate, out);
    k_gates_init<<<dim3(B, 16), 256>>>(x, W_ih, b_ih, b_hh);

    // gates += context @ W_ih[:, :1024]^T + h0 @ W_hh^T (split-K, 512 CTAs)
    k_tc64<<<dim3(G4 / 128, 16), 256>>>(context, W_ih, LSTM_IN, h0, W_hh, H, gates, G4);

    k_lstm_final<<<B, 256>>>(c0, ln_g, ln_b, W_fin, b_fin, out);
}

// round 14
// speedup vs baseline: 1.5000x; 1.0134x over previous
#include <cuda_runtime.h>
#include <cuda_fp16.h>
#include <math.h>
#include <stdint.h>

#define B 64
#define S 512
#define H 1024
#define E 10
#define G4 4096
#define LSTM_IN 1035

// output packing offsets (flattened pytree order)
#define OFF_FIN 0
#define OFF_H   64
#define OFF_C   (64 + B*H)
#define OFF_A   (64 + 2*B*H)
#define OFF_S   (64 + 2*B*H + B*S)

// attn tiling: block 128(bs) x 128(g), BK=32.  A staged in smem (frag-major),
// B fragments loaded directly from L2-resident frag-major mirror via LDG.128.
#define BM 128
#define BN 128
#define BK 32
#define NITER (H / BK)            // 32
#define TILE_B 8192                // one 128x32 fp16 tile, fragment-major
#define STG TILE_B                 // A tile only = 8192 B
#define NST 4
#define R_DP (NST * STG)           // 32768
#define R_WV (R_DP + 512)
#define ATTN_SMEM (R_WV + 512)     // 33792 B -> 2 CTAs/SM easily

#define PADK 36                    // fp32 pad for k_tc64
#define KCH 128                    // split-K chunk for k_tc64

// scratch (no allocation allowed)
__device__ float g_dec_proj[B*H];
__device__ float g_scores[B*S];
__device__ float g_context[B*H];
__device__ float g_gates[B*G4];
__device__ float g_sim[B*E];
__device__ __half g_enc_h[B*S*H];    // fragment-major fp16 mirror of enc
__device__ __half g_wenc_h[H*H];     // fragment-PAIR-major fp16 mirror of W_enc

__device__ __forceinline__ float sigmoidf_(float x) { return 1.f / (1.f + expf(-x)); }

__device__ __forceinline__ uint32_t smem_u32(const void* p) {
    uint32_t a;
    asm("{ .reg .u64 t; cvta.to.shared.u64 t, %1; cvt.u32.u64 %0, t; }" : "=r"(a) : "l"(p));
    return a;
}

__device__ __forceinline__ uint32_t f2tf32(float x) {   // round-to-nearest tf32
    uint32_t r;
    asm("cvt.rna.tf32.f32 %0, %1;" : "=r"(r) : "f"(x));
    return r;
}

__device__ __forceinline__ uint32_t h2u(float x, float y) {
    __half2 h = __floats2half2_rn(x, y);
    return *reinterpret_cast<uint32_t*>(&h);
}

__device__ __forceinline__ void cp_async16(uint32_t dst, const void* src) {
    asm volatile("cp.async.cg.shared.global [%0], [%1], 16;" :: "r"(dst), "l"(src));
}
#define CP_COMMIT() asm volatile("cp.async.commit_group;" ::: "memory")

__device__ __forceinline__ void mma_f16(float c[4], const uint32_t a[4], const uint32_t b[2]) {
    asm volatile(
        "mma.sync.aligned.m16n8k16.row.col.f32.f16.f16.f32 "
        "{%0,%1,%2,%3}, {%4,%5,%6,%7}, {%8,%9}, {%0,%1,%2,%3};\n"
        : "+f"(c[0]), "+f"(c[1]), "+f"(c[2]), "+f"(c[3])
        : "r"(a[0]), "r"(a[1]), "r"(a[2]), "r"(a[3]), "r"(b[0]), "r"(b[1]));
}

__device__ __forceinline__ void mma_tf32(float c[4], const uint32_t a[4], const uint32_t b[2]) {
    asm volatile(
        "mma.sync.aligned.m16n8k8.row.col.f32.tf32.tf32.f32 "
        "{%0,%1,%2,%3}, {%4,%5,%6,%7}, {%8,%9}, {%0,%1,%2,%3};\n"
        : "+f"(c[0]), "+f"(c[1]), "+f"(c[2]), "+f"(c[3])
        : "r"(a[0]), "r"(a[1]), "r"(a[2]), "r"(a[3]), "r"(b[0]), "r"(b[1]));
}

// ---------------------------------------------------------------------------
// Launch 1: fragment-major fp16 mirror of enc + zero accumulators.
// One thread per 16B A-fragment.  grid = B*S*H*2/16/256 = 16384.
// Tile (rb,kb) at byte offset (rb*32+kb)*8192; in-tile frag (k16*8+m16)*512 + lane*16.
// ---------------------------------------------------------------------------
__global__ void k_prep1(const float* __restrict__ enc) {
    int i = blockIdx.x * blockDim.x + threadIdx.x;
    int lane = i & 31;
    int sub  = (i >> 5) & 15;
    int k16  = sub >> 3, m16 = sub & 7;
    int tile = i >> 9;
    int kb   = tile & 31, rb = tile >> 5;
    int g = lane >> 2, t = lane & 3;
    int row = rb * 128 + m16 * 16 + g;
    int kcol = kb * 32 + k16 * 16 + 2 * t;

    const float2* e = (const float2*)enc;
    float2 v0 = e[((size_t)row       * H + kcol    ) >> 1];
    float2 v1 = e[((size_t)(row + 8) * H + kcol    ) >> 1];
    float2 v2 = e[((size_t)row       * H + kcol + 8) >> 1];
    float2 v3 = e[((size_t)(row + 8) * H + kcol + 8) >> 1];
    uint4 o;
    o.x = h2u(v0.x, v0.y);
    o.y = h2u(v1.x, v1.y);
    o.z = h2u(v2.x, v2.y);
    o.w = h2u(v3.x, v3.y);
    ((uint4*)g_enc_h)[i] = o;

    if (i < B*S) g_scores[i] = 0.f;
    if (i < B*H) g_dec_proj[i] = 0.f;
}

// ---------------------------------------------------------------------------
// Launch 2: fragment-PAIR-major fp16 mirror of W_enc.
// One thread per 16B B-fragment-PAIR (sets n8=2p, 2p+1).
// grid = H*H*2/16/256 = 512 blocks.
// Tile (gb,kb) at byte offset (gb*32+kb)*8192; in-tile pair (k16*8+p)*512 + lane*16.
// Lane l (g=l>>2, t=l&3): o.x=(n0,2t..), o.y=(n0,2t+8..), o.z=(n1,2t..), o.w=(n1,2t+8..)
// n0 = gb*128 + 2p*8 + g, n1 = n0 + 8, k = kb*32 + k16*16 + 2t.
// ---------------------------------------------------------------------------
__global__ void k_cvt_w(const float* __restrict__ wenc) {
    int i = blockIdx.x * blockDim.x + threadIdx.x;
    int lane = i & 31;
    int sub  = (i >> 5) & 15;
    int k16  = sub >> 3, pp = sub & 7;
    int tile = i >> 9;
    int kb   = tile & 31, gb = tile >> 5;
    int g = lane >> 2, t = lane & 3;
    int n0 = gb * 128 + pp * 16 + g;
    int n1 = n0 + 8;
    int k = kb * 32 + k16 * 16 + 2 * t;

    const float2* w = (const float2*)wenc;
    float2 u0 = w[((size_t)n0 * H + k    ) >> 1];
    float2 u1 = w[((size_t)n0 * H + k + 8) >> 1];
    float2 u2 = w[((size_t)n1 * H + k    ) >> 1];
    float2 u3 = w[((size_t)n1 * H + k + 8) >> 1];
    uint4 o;
    o.x = h2u(u0.x, u0.y);
    o.y = h2u(u1.x, u1.y);
    o.z = h2u(u2.x, u2.y);
    o.w = h2u(u3.x, u3.y);
    ((uint4*)g_wenc_h)[i] = o;
}

// ---------------------------------------------------------------------------
// fp16 fused attention-score GEMM.  A via cp.async smem stages (frag-major);
// B fragments via direct LDG.128 from L2-resident pair-major mirror.
// Block tile 128 x 128, 8 warps as 2M x 4N (warp tile 64x32). 2 CTAs/SM.
// grid = (H/BN = 8 [g fastest, L2 reuse], B*S/BM = 256)
// ---------------------------------------------------------------------------
__global__ void __launch_bounds__(256, 2) k_attn_f16(
    const __half* __restrict__ ench,
    const __half* __restrict__ wench,
    const float* __restrict__ w_val)
{
    extern __shared__ char smem[];
    const uint32_t sb = smem_u32(smem);
    const int tid = threadIdx.x;
    const int lane = tid & 31, warp = tid >> 5;
    const int warpM = warp & 1, warpN = warp >> 1;
    const int group = lane >> 2, tid4 = lane & 3;

    const int gb = blockIdx.x;
    const int rb = blockIdx.y;
    const int gBase   = gb * BN;
    const int rowBase = rb * BM;
    const int b = rowBase / S;

    float* dp_s = (float*)(smem + R_DP);
    float* wv_s = (float*)(smem + R_WV);
    if (tid < BN) {
        dp_s[tid] = g_dec_proj[b*H + gBase + tid];
        wv_s[tid] = w_val[gBase + tid];
    }

    const char* Asrc = (const char*)ench  + (size_t)rb * 32 * TILE_B;
    const char* Bsrc = (const char*)wench + (size_t)gb * 32 * TILE_B;

    auto issue = [&](int it, int stg) {
        uint32_t sa = sb + stg * STG;
        const char* a = Asrc + (size_t)it * TILE_B;
#pragma unroll
        for (int i = 0; i < 2; i++) {
            int c = (tid + 256 * i) * 16;
            cp_async16(sa + c, a + c);
        }
        CP_COMMIT();
    };

    float acc[4][4][4];
#pragma unroll
    for (int mi = 0; mi < 4; mi++)
#pragma unroll
        for (int ni = 0; ni < 4; ni++)
#pragma unroll
            for (int q = 0; q < 4; q++) acc[mi][ni][q] = 0.f;

    issue(0, 0);
    issue(1, 1);
    issue(2, 2);

    for (int it = 0; it < NITER; it++) {
        // B fragment pairs for this iter straight from L2 (pair-major mirror)
        const uint4* Bt = (const uint4*)(Bsrc + (size_t)it * TILE_B);
        uint4 bb[2][2];
#pragma unroll
        for (int k16 = 0; k16 < 2; k16++)
#pragma unroll
            for (int p = 0; p < 2; p++)
                bb[k16][p] = __ldg(&Bt[(k16*8 + warpN*2 + p) * 32 + lane]);

        if (it <= NITER - 3)      { asm volatile("cp.async.wait_group 2;" ::: "memory"); }
        else if (it == NITER - 2) { asm volatile("cp.async.wait_group 1;" ::: "memory"); }
        else                      { asm volatile("cp.async.wait_group 0;" ::: "memory"); }
        __syncthreads();
        if (it + 3 < NITER) issue(it + 3, (it + 3) & 3);

        const char* stg = smem + (it & 3) * STG;

#pragma unroll
        for (int k16 = 0; k16 < 2; k16++) {
            uint4 afr[4];
#pragma unroll
            for (int mi = 0; mi < 4; mi++)
                afr[mi] = *(const uint4*)(stg +
                    ((k16*8 + warpM*4 + mi) * 32 + lane) * 16);
#pragma unroll
            for (int p = 0; p < 2; p++) {
                const uint32_t* bp = reinterpret_cast<const uint32_t*>(&bb[k16][p]);
#pragma unroll
                for (int mi = 0; mi < 4; mi++) {
                    mma_f16(acc[mi][2*p    ],
                            reinterpret_cast<const uint32_t*>(&afr[mi]), bp);
                    mma_f16(acc[mi][2*p + 1],
                            reinterpret_cast<const uint32_t*>(&afr[mi]), bp + 2);
                }
            }
        }
    }

    __syncthreads();

    // epilogue: tanh + w_val dot over warp's 32 g-cols, quad shfl reduce, atomic
#pragma unroll
    for (int mi = 0; mi < 4; mi++) {
        float p0 = 0.f, p1 = 0.f;
#pragma unroll
        for (int ni = 0; ni < 4; ni++)
#pragma unroll
            for (int q = 0; q < 2; q++) {
                int g = warpN*32 + ni*8 + 2*tid4 + q;
                float wv = wv_s[g], dp = dp_s[g];
                p0 += wv * tanhf(acc[mi][ni][q    ] + dp);
                p1 += wv * tanhf(acc[mi][ni][2 + q] + dp);
            }
        p0 += __shfl_down_sync(0xffffffffu, p0, 2, 4);
        p0 += __shfl_down_sync(0xffffffffu, p0, 1, 4);
        p1 += __shfl_down_sync(0xffffffffu, p1, 2, 4);
        p1 += __shfl_down_sync(0xffffffffu, p1, 1, 4);
        if (tid4 == 0) {
            int row = rowBase + warpM*64 + mi*16 + group;
            atomicAdd(&g_scores[row    ], p0);
            atomicAdd(&g_scores[row + 8], p1);
        }
    }
}

// ---------------------------------------------------------------------------
// Split-K 64-row GEMM on tensor cores (tf32, RN operands), atomic epilogue.
// grid = (N/128, nChunks).  src = chunk>>3, kb = (chunk&7)*KCH.
// ---------------------------------------------------------------------------
__global__ void __launch_bounds__(256) k_tc64(
    const float* __restrict__ A0, const float* __restrict__ W0, int ldw0,
    const float* __restrict__ A1, const float* __restrict__ W1, int ldw1,
    float* __restrict__ C, int ldc)
{
    __shared__ float As[64 * PADK];
    __shared__ float Ws[128 * PADK];
    const int tid = threadIdx.x;
    const int lane = tid & 31, warp = tid >> 5;
    const int warpM = warp & 1, warpN = warp >> 1;
    const int group = lane >> 2, tid4 = lane & 3;
    const int nBase = blockIdx.x * 128;
    const int chunk = blockIdx.y;

    const float* A = (chunk >= 8) ? A1 : A0;
    const float* W = (chunk >= 8) ? W1 : W0;
    const int ldw  = (chunk >= 8) ? ldw1 : ldw0;
    const int kb = (chunk & 7) * KCH;

    float acc[2][4][4];
#pragma unroll
    for (int mi = 0; mi < 2; mi++)
#pragma unroll
        for (int ni = 0; ni < 4; ni++)
#pragma unroll
            for (int q = 0; q < 4; q++) acc[mi][ni][q] = 0.f;

    for (int k0 = kb; k0 < kb + KCH; k0 += 32) {
#pragma unroll
        for (int i = 0; i < 8; i++) {
            int e = tid + 256 * i;
            As[(e >> 5) * PADK + (e & 31)] =
                __uint_as_float(f2tf32(A[(size_t)(e >> 5) * H + k0 + (e & 31)]));
        }
#pragma unroll
        for (int i = 0; i < 16; i++) {
            int e = tid + 256 * i;
            Ws[(e >> 5) * PADK + (e & 31)] =
                __uint_as_float(f2tf32(W[(size_t)(nBase + (e >> 5)) * ldw + k0 + (e & 31)]));
        }
        __syncthreads();
#pragma unroll
        for (int k8 = 0; k8 < 4; k8++) {
            int kk = k8 * 8;
            uint32_t afr[2][4], bfr[4][2];
#pragma unroll
            for (int mi = 0; mi < 2; mi++) {
                int m = warpM*32 + mi*16 + group;
                afr[mi][0] = __float_as_uint(As[(m    )*PADK + kk + tid4    ]);
                afr[mi][1] = __float_as_uint(As[(m + 8)*PADK + kk + tid4    ]);
                afr[mi][2] = __float_as_uint(As[(m    )*PADK + kk + tid4 + 4]);
                afr[mi][3] = __float_as_uint(As[(m + 8)*PADK + kk + tid4 + 4]);
            }
#pragma unroll
            for (int ni = 0; ni < 4; ni++) {
                int n = warpN*32 + ni*8 + group;
                bfr[ni][0] = __float_as_uint(Ws[n*PADK + kk + tid4    ]);
                bfr[ni][1] = __float_as_uint(Ws[n*PADK + kk + tid4 + 4]);
            }
#pragma unroll
            for (int mi = 0; mi < 2; mi++)
#pragma unroll
                for (int ni = 0; ni < 4; ni++)
                    mma_tf32(acc[mi][ni], afr[mi], bfr[ni]);
        }
        __syncthreads();
    }

#pragma unroll
    for (int mi = 0; mi < 2; mi++)
#pragma unroll
        for (int ni = 0; ni < 4; ni++) {
            int row = warpM*32 + mi*16 + group;
            int col = nBase + warpN*32 + ni*8 + 2*tid4;
            atomicAdd(&C[(size_t)row*ldc + col],         acc[mi][ni][0]);
            atomicAdd(&C[(size_t)row*ldc + col + 1],     acc[mi][ni][1]);
            atomicAdd(&C[(size_t)(row+8)*ldc + col],     acc[mi][ni][2]);
            atomicAdd(&C[(size_t)(row+8)*ldc + col + 1], acc[mi][ni][3]);
        }
}

// ---------------------------------------------------------------------------
__global__ void k_softmax(float* __restrict__ out)
{
    int b = blockIdx.x, tid = threadIdx.x;
    __shared__ float red[256];
    float s0 = g_scores[b*S + tid];
    float s1 = g_scores[b*S + 256 + tid];
    red[tid] = fmaxf(s0, s1);
    __syncthreads();
    for (int off = 128; off > 0; off >>= 1) {
        if (tid < off) red[tid] = fmaxf(red[tid], red[tid + off]);
        __syncthreads();
    }
    float m = red[0];
    __syncthreads();
    float e0 = expf(s0 - m), e1 = expf(s1 - m);
    red[tid] = e0 + e1;
    __syncthreads();
    for (int off = 128; off > 0; off >>= 1) {
        if (tid < off) red[tid] += red[tid + off];
        __syncthreads();
    }
    float inv = 1.f / red[0];
    out[OFF_A + b*S + tid]       = e0 * inv;
    out[OFF_A + b*S + 256 + tid] = e1 * inv;
}

// ---------------------------------------------------------------------------
// context from fp32 enc.  grid (B, 4) x 256.
__global__ void k_context(const float* __restrict__ enc, const float* __restrict__ out)
{
    int b = blockIdx.x;
    int h = blockIdx.y * 256 + threadIdx.x;
    __shared__ float w[S];
    for (int s = threadIdx.x; s < S; s += 256) w[s] = out[OFF_A + b*S + s];
    __syncthreads();
    const float* p = enc + (size_t)b * S * H + h;
    float a0 = 0.f, a1 = 0.f, a2 = 0.f, a3 = 0.f;
#pragma unroll 4
    for (int s = 0; s < S; s += 4) {
        a0 += w[s]     * p[(size_t)s * H];
        a1 += w[s + 1] * p[(size_t)(s + 1) * H];
        a2 += w[s + 2] * p[(size_t)(s + 2) * H];
        a3 += w[s + 3] * p[(size_t)(s + 3) * H];
    }
    g_context[b*H + h] = (a0 + a1) + (a2 + a3);
}

// ---------------------------------------------------------------------------
__global__ void k_sim(const float* __restrict__ events,
                      const float* __restrict__ W_gate,
                      float* __restrict__ out)
{
    int b = blockIdx.x;
    int tid = threadIdx.x, warp = tid >> 5, lane = tid & 31;
    __shared__ float t[E];
    if (warp < E) {
        float acc = 0.f;
        for (int h = lane; h < H; h += 32)
            acc += g_context[b*H + h] * events[warp*H + h];
#pragma unroll
        for (int off = 16; off > 0; off >>= 1)
            acc += __shfl_down_sync(0xffffffffu, acc, off);
        if (lane == 0) t[warp] = acc;
    }
    __syncthreads();
    if (tid < E) {
        float s = 0.f;
#pragma unroll
        for (int e = 0; e < E; e++) s += t[e] * W_gate[tid*E + e];
        g_sim[b*E + tid] = s;
        out[OFF_S + b*E + tid] = s;
    }
}

// ---------------------------------------------------------------------------
__global__ void k_gates_init(const float* __restrict__ x,
                             const float* __restrict__ W_ih,
                             const float* __restrict__ b_ih,
                             const float* __restrict__ b_hh)
{
    int b = blockIdx.x;
    int j = blockIdx.y * 256 + threadIdx.x;
    const float* wr = W_ih + (size_t)j * LSTM_IN;
    float v = b_ih[j] + b_hh[j] + x[b] * wr[1034];
#pragma unroll
    for (int e = 0; e < E; e++) v += g_sim[b*E + e] * wr[1024 + e];
    g_gates[b*G4 + j] = v;
}

// ---------------------------------------------------------------------------
__global__ void k_lstm_final(const float* __restrict__ c0,
                             const float* __restrict__ ln_g,
                             const float* __restrict__ ln_b,
                             const float* __restrict__ W_fin,
                             const float* __restrict__ b_fin,
                             float* __restrict__ out)
{
    int b = blockIdx.x, tid = threadIdx.x;
    __shared__ float red[256];
    float hv[4];
    float sum = 0.f;
#pragma unroll
    for (int r = 0; r < 4; r++) {
        int h = r*256 + tid;
        float ig = g_gates[b*G4 + h];
        float fg = g_gates[b*G4 + 1024 + h];
        float gg = g_gates[b*G4 + 2048 + h];
        float og = g_gates[b*G4 + 3072 + h];
        float cn = sigmoidf_(fg) * c0[b*H + h] + sigmoidf_(ig) * tanhf(gg);
        float hn = sigmoidf_(og) * tanhf(cn);
        out[OFF_H + b*H + h] = hn;
        out[OFF_C + b*H + h] = cn;
        hv[r] = hn;
        sum += hn;
    }
    red[tid] = sum; __syncthreads();
    for (int off = 128; off > 0; off >>= 1) {
        if (tid < off) red[tid] += red[tid + off];
        __syncthreads();
    }
    float mu = red[0] * (1.f / H);
    __syncthreads();
    float sq = 0.f;
#pragma unroll
    for (int r = 0; r < 4; r++) { float d = hv[r] - mu; sq += d * d; }
    red[tid] = sq; __syncthreads();
    for (int off = 128; off > 0; off >>= 1) {
        if (tid < off) red[tid] += red[tid + off];
        __syncthreads();
    }
    float rstd = rsqrtf(red[0] * (1.f / H) + 1e-5f);
    __syncthreads();
    float fp = 0.f;
#pragma unroll
    for (int r = 0; r < 4; r++) {
        int h = r*256 + tid;
        float y = (hv[r] - mu) * rstd * ln_g[h] + ln_b[h];
        fp += y * W_fin[h];
    }
    red[tid] = fp; __syncthreads();
    for (int off = 128; off > 0; off >>= 1) {
        if (tid < off) red[tid] += red[tid + off];
        __syncthreads();
    }
    if (tid == 0) out[OFF_FIN + b] = red[0] + b_fin[0];
}

// ---------------------------------------------------------------------------
extern "C" void kernel_launch(void* const* d_in, const int* in_sizes, int n_in,
                              void* d_out, int out_size)
{
    const float* x      = (const float*)d_in[0];
    const float* h0     = (const float*)d_in[1];
    const float* c0     = (const float*)d_in[2];
    const float* enc    = (const float*)d_in[3];
    const float* W_enc  = (const float*)d_in[4];
    const float* W_dec  = (const float*)d_in[5];
    const float* w_val  = (const float*)d_in[6];
    const float* W_gate = (const float*)d_in[7];
    const float* events = (const float*)d_in[8];
    const float* W_ih   = (const float*)d_in[9];
    const float* W_hh   = (const float*)d_in[10];
    const float* b_ih   = (const float*)d_in[11];
    const float* b_hh   = (const float*)d_in[12];
    const float* ln_g   = (const float*)d_in[13];
    const float* ln_b   = (const float*)d_in[14];
    const float* W_fin  = (const float*)d_in[15];
    const float* b_fin  = (const float*)d_in[16];
    float* out = (float*)d_out;

    void* p;
    cudaGetSymbolAddress(&p, g_dec_proj); float*  dec_proj = (float*)p;
    cudaGetSymbolAddress(&p, g_context);  float*  context  = (float*)p;
    cudaGetSymbolAddress(&p, g_gates);    float*  gates    = (float*)p;
    cudaGetSymbolAddress(&p, g_enc_h);    __half* ench     = (__half*)p;
    cudaGetSymbolAddress(&p, g_wenc_h);   __half* wench    = (__half*)p;

    cudaFuncSetAttribute(k_attn_f16, cudaFuncAttributeMaxDynamicSharedMemorySize, ATTN_SMEM);

    // launch 1: fragment-major enc mirror + zeroing
    k_prep1<<<B*S*H*2/16/256, 256>>>(enc);
    // launch 2: fragment-pair-major W_enc mirror
    k_cvt_w<<<H*H*2/16/256, 256>>>(W_enc);
    // launch 3: dec_proj = h0 @ W_dec^T (tf32, split-K)
    k_tc64<<<dim3(H / 128, 8), 256>>>(h0, W_dec, H, nullptr, nullptr, 0, dec_proj, H);
    // launch 4: fused scores (ncu profiles this one)
    k_attn_f16<<<dim3(H / BN, B * S / BM), 256, ATTN_SMEM>>>(ench, wench, w_val);

    k_softmax<<<B, 256>>>(out);
    k_context<<<dim3(B, H / 256), 256>>>(enc, out);
    k_sim<<<B, 320>>>(events, W_gate, out);
    k_gates_init<<<dim3(B, 16), 256>>>(x, W_ih, b_ih, b_hh);

    // gates += context @ W_ih[:, :1024]^T + h0 @ W_hh^T (split-K, 512 CTAs)
    k_tc64<<<dim3(G4 / 128, 16), 256>>>(context, W_ih, LSTM_IN, h0, W_hh, H, gates, G4);

    k_lstm_final<<<B, 256>>>(c0, ln_g, ln_b, W_fin, b_fin, out);
}

// round 15
// speedup vs baseline: 1.6061x; 1.0708x over previous
#include <cuda_runtime.h>
#include <cuda_fp16.h>
#include <math.h>
#include <stdint.h>

#define B 64
#define S 512
#define H 1024
#define E 10
#define G4 4096
#define LSTM_IN 1035

// output packing offsets (flattened pytree order)
#define OFF_FIN 0
#define OFF_H   64
#define OFF_C   (64 + B*H)
#define OFF_A   (64 + 2*B*H)
#define OFF_S   (64 + 2*B*H + B*S)

// attn tiling: block 128(bs) x 128(g), BK=32.  A staged in smem (frag-major),
// B fragments loaded directly from L2-resident pair-major mirror via LDG.128.
#define BM 128
#define BN 128
#define BK 32
#define NITER (H / BK)            // 32
#define TILE_B 8192                // one 128x32 fp16 tile, fragment-major
#define STG TILE_B                 // A tile only = 8192 B
#define NST 4
#define R_DP (NST * STG)           // 32768
#define R_WV (R_DP + 512)
#define ATTN_SMEM (R_WV + 512)     // 33792 B -> 2 CTAs/SM

#define PADK 36                    // fp32 pad for k_tc64
#define KCH 128                    // split-K chunk for k_tc64

// scratch (no allocation allowed)
__device__ float g_dec_proj[B*H];
__device__ float g_scores[B*S];
__device__ float g_context[B*H];
__device__ float g_gates[B*G4];
__device__ float g_sim[B*E];
__device__ __half g_enc_h[B*S*H];    // fragment-major fp16 mirror of enc
__device__ __half g_wenc_h[H*H];     // fragment-PAIR-major fp16 mirror of W_enc

__device__ __forceinline__ float sigmoidf_(float x) { return 1.f / (1.f + expf(-x)); }

__device__ __forceinline__ uint32_t smem_u32(const void* p) {
    uint32_t a;
    asm("{ .reg .u64 t; cvta.to.shared.u64 t, %1; cvt.u32.u64 %0, t; }" : "=r"(a) : "l"(p));
    return a;
}

__device__ __forceinline__ uint32_t f2tf32(float x) {   // round-to-nearest tf32
    uint32_t r;
    asm("cvt.rna.tf32.f32 %0, %1;" : "=r"(r) : "f"(x));
    return r;
}

__device__ __forceinline__ uint32_t h2u(float x, float y) {
    __half2 h = __floats2half2_rn(x, y);
    return *reinterpret_cast<uint32_t*>(&h);
}

__device__ __forceinline__ float2 u2f2(uint32_t u) {
    __half2 h = *reinterpret_cast<__half2*>(&u);
    return __half22float2(h);
}

__device__ __forceinline__ void cp_async16(uint32_t dst, const void* src) {
    asm volatile("cp.async.cg.shared.global [%0], [%1], 16;" :: "r"(dst), "l"(src));
}
#define CP_COMMIT() asm volatile("cp.async.commit_group;" ::: "memory")

__device__ __forceinline__ void mma_f16(float c[4], const uint32_t a[4], const uint32_t b[2]) {
    asm volatile(
        "mma.sync.aligned.m16n8k16.row.col.f32.f16.f16.f32 "
        "{%0,%1,%2,%3}, {%4,%5,%6,%7}, {%8,%9}, {%0,%1,%2,%3};\n"
        : "+f"(c[0]), "+f"(c[1]), "+f"(c[2]), "+f"(c[3])
        : "r"(a[0]), "r"(a[1]), "r"(a[2]), "r"(a[3]), "r"(b[0]), "r"(b[1]));
}

__device__ __forceinline__ void mma_tf32(float c[4], const uint32_t a[4], const uint32_t b[2]) {
    asm volatile(
        "mma.sync.aligned.m16n8k8.row.col.f32.tf32.tf32.f32 "
        "{%0,%1,%2,%3}, {%4,%5,%6,%7}, {%8,%9}, {%0,%1,%2,%3};\n"
        : "+f"(c[0]), "+f"(c[1]), "+f"(c[2]), "+f"(c[3])
        : "r"(a[0]), "r"(a[1]), "r"(a[2]), "r"(a[3]), "r"(b[0]), "r"(b[1]));
}

// ---------------------------------------------------------------------------
// Launch 1: fragment-major fp16 mirror of enc + zero accumulators.
// One thread per 16B A-fragment.  grid = 16384.
// Tile (rb,kb) at byte offset (rb*32+kb)*8192; in-tile uint4 = (k16*8+m16)*32 + lane.
// Lane l (g=l>>2, t=l&3): o.x=(r,2t..), o.y=(r+8,2t..), o.z=(r,2t+8..), o.w=(r+8,2t+8..)
// r = rb*128 + m16*16 + g, k base = kb*32 + k16*16.
// ---------------------------------------------------------------------------
__global__ void k_prep1(const float* __restrict__ enc) {
    int i = blockIdx.x * blockDim.x + threadIdx.x;
    int lane = i & 31;
    int sub  = (i >> 5) & 15;
    int k16  = sub >> 3, m16 = sub & 7;
    int tile = i >> 9;
    int kb   = tile & 31, rb = tile >> 5;
    int g = lane >> 2, t = lane & 3;
    int row = rb * 128 + m16 * 16 + g;
    int kcol = kb * 32 + k16 * 16 + 2 * t;

    const float2* e = (const float2*)enc;
    float2 v0 = e[((size_t)row       * H + kcol    ) >> 1];
    float2 v1 = e[((size_t)(row + 8) * H + kcol    ) >> 1];
    float2 v2 = e[((size_t)row       * H + kcol + 8) >> 1];
    float2 v3 = e[((size_t)(row + 8) * H + kcol + 8) >> 1];
    uint4 o;
    o.x = h2u(v0.x, v0.y);
    o.y = h2u(v1.x, v1.y);
    o.z = h2u(v2.x, v2.y);
    o.w = h2u(v3.x, v3.y);
    ((uint4*)g_enc_h)[i] = o;

    if (i < B*S) g_scores[i] = 0.f;
    if (i < B*H) g_dec_proj[i] = 0.f;
}

// ---------------------------------------------------------------------------
// Launch 2: fragment-PAIR-major fp16 mirror of W_enc.  grid = 512.
// ---------------------------------------------------------------------------
__global__ void k_cvt_w(const float* __restrict__ wenc) {
    int i = blockIdx.x * blockDim.x + threadIdx.x;
    int lane = i & 31;
    int sub  = (i >> 5) & 15;
    int k16  = sub >> 3, pp = sub & 7;
    int tile = i >> 9;
    int kb   = tile & 31, gb = tile >> 5;
    int g = lane >> 2, t = lane & 3;
    int n0 = gb * 128 + pp * 16 + g;
    int n1 = n0 + 8;
    int k = kb * 32 + k16 * 16 + 2 * t;

    const float2* w = (const float2*)wenc;
    float2 u0 = w[((size_t)n0 * H + k    ) >> 1];
    float2 u1 = w[((size_t)n0 * H + k + 8) >> 1];
    float2 u2 = w[((size_t)n1 * H + k    ) >> 1];
    float2 u3 = w[((size_t)n1 * H + k + 8) >> 1];
    uint4 o;
    o.x = h2u(u0.x, u0.y);
    o.y = h2u(u1.x, u1.y);
    o.z = h2u(u2.x, u2.y);
    o.w = h2u(u3.x, u3.y);
    ((uint4*)g_wenc_h)[i] = o;
}

// ---------------------------------------------------------------------------
// fp16 fused attention-score GEMM (R14 champion, unchanged).
// ---------------------------------------------------------------------------
__global__ void __launch_bounds__(256, 2) k_attn_f16(
    const __half* __restrict__ ench,
    const __half* __restrict__ wench,
    const float* __restrict__ w_val)
{
    extern __shared__ char smem[];
    const uint32_t sb = smem_u32(smem);
    const int tid = threadIdx.x;
    const int lane = tid & 31, warp = tid >> 5;
    const int warpM = warp & 1, warpN = warp >> 1;
    const int group = lane >> 2, tid4 = lane & 3;

    const int gb = blockIdx.x;
    const int rb = blockIdx.y;
    const int gBase   = gb * BN;
    const int rowBase = rb * BM;
    const int b = rowBase / S;

    float* dp_s = (float*)(smem + R_DP);
    float* wv_s = (float*)(smem + R_WV);
    if (tid < BN) {
        dp_s[tid] = g_dec_proj[b*H + gBase + tid];
        wv_s[tid] = w_val[gBase + tid];
    }

    const char* Asrc = (const char*)ench  + (size_t)rb * 32 * TILE_B;
    const char* Bsrc = (const char*)wench + (size_t)gb * 32 * TILE_B;

    auto issue = [&](int it, int stg) {
        uint32_t sa = sb + stg * STG;
        const char* a = Asrc + (size_t)it * TILE_B;
#pragma unroll
        for (int i = 0; i < 2; i++) {
            int c = (tid + 256 * i) * 16;
            cp_async16(sa + c, a + c);
        }
        CP_COMMIT();
    };

    float acc[4][4][4];
#pragma unroll
    for (int mi = 0; mi < 4; mi++)
#pragma unroll
        for (int ni = 0; ni < 4; ni++)
#pragma unroll
            for (int q = 0; q < 4; q++) acc[mi][ni][q] = 0.f;

    issue(0, 0);
    issue(1, 1);
    issue(2, 2);

    for (int it = 0; it < NITER; it++) {
        const uint4* Bt = (const uint4*)(Bsrc + (size_t)it * TILE_B);
        uint4 bb[2][2];
#pragma unroll
        for (int k16 = 0; k16 < 2; k16++)
#pragma unroll
            for (int p = 0; p < 2; p++)
                bb[k16][p] = __ldg(&Bt[(k16*8 + warpN*2 + p) * 32 + lane]);

        if (it <= NITER - 3)      { asm volatile("cp.async.wait_group 2;" ::: "memory"); }
        else if (it == NITER - 2) { asm volatile("cp.async.wait_group 1;" ::: "memory"); }
        else                      { asm volatile("cp.async.wait_group 0;" ::: "memory"); }
        __syncthreads();
        if (it + 3 < NITER) issue(it + 3, (it + 3) & 3);

        const char* stg = smem + (it & 3) * STG;

#pragma unroll
        for (int k16 = 0; k16 < 2; k16++) {
            uint4 afr[4];
#pragma unroll
            for (int mi = 0; mi < 4; mi++)
                afr[mi] = *(const uint4*)(stg +
                    ((k16*8 + warpM*4 + mi) * 32 + lane) * 16);
#pragma unroll
            for (int p = 0; p < 2; p++) {
                const uint32_t* bp = reinterpret_cast<const uint32_t*>(&bb[k16][p]);
#pragma unroll
                for (int mi = 0; mi < 4; mi++) {
                    mma_f16(acc[mi][2*p    ],
                            reinterpret_cast<const uint32_t*>(&afr[mi]), bp);
                    mma_f16(acc[mi][2*p + 1],
                            reinterpret_cast<const uint32_t*>(&afr[mi]), bp + 2);
                }
            }
        }
    }

    __syncthreads();

#pragma unroll
    for (int mi = 0; mi < 4; mi++) {
        float p0 = 0.f, p1 = 0.f;
#pragma unroll
        for (int ni = 0; ni < 4; ni++)
#pragma unroll
            for (int q = 0; q < 2; q++) {
                int g = warpN*32 + ni*8 + 2*tid4 + q;
                float wv = wv_s[g], dp = dp_s[g];
                p0 += wv * tanhf(acc[mi][ni][q    ] + dp);
                p1 += wv * tanhf(acc[mi][ni][2 + q] + dp);
            }
        p0 += __shfl_down_sync(0xffffffffu, p0, 2, 4);
        p0 += __shfl_down_sync(0xffffffffu, p0, 1, 4);
        p1 += __shfl_down_sync(0xffffffffu, p1, 2, 4);
        p1 += __shfl_down_sync(0xffffffffu, p1, 1, 4);
        if (tid4 == 0) {
            int row = rowBase + warpM*64 + mi*16 + group;
            atomicAdd(&g_scores[row    ], p0);
            atomicAdd(&g_scores[row + 8], p1);
        }
    }
}

// ---------------------------------------------------------------------------
// Split-K 64-row GEMM on tensor cores (tf32, RN operands), atomic epilogue.
// ---------------------------------------------------------------------------
__global__ void __launch_bounds__(256) k_tc64(
    const float* __restrict__ A0, const float* __restrict__ W0, int ldw0,
    const float* __restrict__ A1, const float* __restrict__ W1, int ldw1,
    float* __restrict__ C, int ldc)
{
    __shared__ float As[64 * PADK];
    __shared__ float Ws[128 * PADK];
    const int tid = threadIdx.x;
    const int lane = tid & 31, warp = tid >> 5;
    const int warpM = warp & 1, warpN = warp >> 1;
    const int group = lane >> 2, tid4 = lane & 3;
    const int nBase = blockIdx.x * 128;
    const int chunk = blockIdx.y;

    const float* A = (chunk >= 8) ? A1 : A0;
    const float* W = (chunk >= 8) ? W1 : W0;
    const int ldw  = (chunk >= 8) ? ldw1 : ldw0;
    const int kb = (chunk & 7) * KCH;

    float acc[2][4][4];
#pragma unroll
    for (int mi = 0; mi < 2; mi++)
#pragma unroll
        for (int ni = 0; ni < 4; ni++)
#pragma unroll
            for (int q = 0; q < 4; q++) acc[mi][ni][q] = 0.f;

    for (int k0 = kb; k0 < kb + KCH; k0 += 32) {
#pragma unroll
        for (int i = 0; i < 8; i++) {
            int e = tid + 256 * i;
            As[(e >> 5) * PADK + (e & 31)] =
                __uint_as_float(f2tf32(A[(size_t)(e >> 5) * H + k0 + (e & 31)]));
        }
#pragma unroll
        for (int i = 0; i < 16; i++) {
            int e = tid + 256 * i;
            Ws[(e >> 5) * PADK + (e & 31)] =
                __uint_as_float(f2tf32(W[(size_t)(nBase + (e >> 5)) * ldw + k0 + (e & 31)]));
        }
        __syncthreads();
#pragma unroll
        for (int k8 = 0; k8 < 4; k8++) {
            int kk = k8 * 8;
            uint32_t afr[2][4], bfr[4][2];
#pragma unroll
            for (int mi = 0; mi < 2; mi++) {
                int m = warpM*32 + mi*16 + group;
                afr[mi][0] = __float_as_uint(As[(m    )*PADK + kk + tid4    ]);
                afr[mi][1] = __float_as_uint(As[(m + 8)*PADK + kk + tid4    ]);
                afr[mi][2] = __float_as_uint(As[(m    )*PADK + kk + tid4 + 4]);
                afr[mi][3] = __float_as_uint(As[(m + 8)*PADK + kk + tid4 + 4]);
            }
#pragma unroll
            for (int ni = 0; ni < 4; ni++) {
                int n = warpN*32 + ni*8 + group;
                bfr[ni][0] = __float_as_uint(Ws[n*PADK + kk + tid4    ]);
                bfr[ni][1] = __float_as_uint(Ws[n*PADK + kk + tid4 + 4]);
            }
#pragma unroll
            for (int mi = 0; mi < 2; mi++)
#pragma unroll
                for (int ni = 0; ni < 4; ni++)
                    mma_tf32(acc[mi][ni], afr[mi], bfr[ni]);
        }
        __syncthreads();
    }

#pragma unroll
    for (int mi = 0; mi < 2; mi++)
#pragma unroll
        for (int ni = 0; ni < 4; ni++) {
            int row = warpM*32 + mi*16 + group;
            int col = nBase + warpN*32 + ni*8 + 2*tid4;
            atomicAdd(&C[(size_t)row*ldc + col],         acc[mi][ni][0]);
            atomicAdd(&C[(size_t)row*ldc + col + 1],     acc[mi][ni][1]);
            atomicAdd(&C[(size_t)(row+8)*ldc + col],     acc[mi][ni][2]);
            atomicAdd(&C[(size_t)(row+8)*ldc + col + 1], acc[mi][ni][3]);
        }
}

// ---------------------------------------------------------------------------
__global__ void k_softmax(float* __restrict__ out)
{
    int b = blockIdx.x, tid = threadIdx.x;
    __shared__ float red[256];
    float s0 = g_scores[b*S + tid];
    float s1 = g_scores[b*S + 256 + tid];
    red[tid] = fmaxf(s0, s1);
    __syncthreads();
    for (int off = 128; off > 0; off >>= 1) {
        if (tid < off) red[tid] = fmaxf(red[tid], red[tid + off]);
        __syncthreads();
    }
    float m = red[0];
    __syncthreads();
    float e0 = expf(s0 - m), e1 = expf(s1 - m);
    red[tid] = e0 + e1;
    __syncthreads();
    for (int off = 128; off > 0; off >>= 1) {
        if (tid < off) red[tid] += red[tid + off];
        __syncthreads();
    }
    float inv = 1.f / red[0];
    out[OFF_A + b*S + tid]       = e0 * inv;
    out[OFF_A + b*S + 256 + tid] = e1 * inv;
}

// ---------------------------------------------------------------------------
// context from fragment-major fp16 mirror, register-accumulated.
// grid = (B * 4) CTAs: b = blk>>2, kb range = (blk&3)*8 .. +8.  block = 256.
// Warp w: k16 = w&1, kb_local = (w>>1)*2 + {0,1}.  Accumulates its 4 k-positions
// over all 4 rb tiles x 8 m16 in registers (64 coalesced 512B loads), then one
// 12-shuffle g-reduction and DIRECT stores (disjoint k per warp, no atomics).
// ---------------------------------------------------------------------------
__global__ void __launch_bounds__(256) k_ctx(
    const __half* __restrict__ ench, const float* __restrict__ out)
{
    __shared__ float w[S];
    const int blk = blockIdx.x;
    const int b = blk >> 2;
    const int split = blk & 3;
    const int tid = threadIdx.x;
    const int warp = tid >> 5, lane = tid & 31;
    const int g = lane >> 2;
    const int k16 = warp & 1;

    w[tid]       = out[OFF_A + b*S + tid];
    w[tid + 256] = out[OFF_A + b*S + 256 + tid];
    __syncthreads();

#pragma unroll
    for (int kbi = 0; kbi < 2; kbi++) {
        const int kb = split*8 + (warp >> 1)*2 + kbi;
        float c0 = 0.f, c1 = 0.f, c2 = 0.f, c3 = 0.f;
#pragma unroll
        for (int rb4 = 0; rb4 < 4; rb4++) {
            const int rb = b*4 + rb4;
            const uint4* tile = (const uint4*)((const char*)ench +
                                 ((size_t)rb * 32 + kb) * TILE_B);
            const float* wr = &w[rb4 * 128 + g];
#pragma unroll
            for (int m16 = 0; m16 < 8; m16++) {
                uint4 o = tile[(k16*8 + m16)*32 + lane];
                float2 x0 = u2f2(o.x);
                float2 x1 = u2f2(o.y);
                float2 x2 = u2f2(o.z);
                float2 x3 = u2f2(o.w);
                float w0 = wr[m16*16];
                float w1 = wr[m16*16 + 8];
                c0 += w0*x0.x + w1*x1.x;
                c1 += w0*x0.y + w1*x1.y;
                c2 += w0*x2.x + w1*x3.x;
                c3 += w0*x2.y + w1*x3.y;
            }
        }
#pragma unroll
        for (int off = 16; off >= 4; off >>= 1) {
            c0 += __shfl_down_sync(0xffffffffu, c0, off);
            c1 += __shfl_down_sync(0xffffffffu, c1, off);
            c2 += __shfl_down_sync(0xffffffffu, c2, off);
            c3 += __shfl_down_sync(0xffffffffu, c3, off);
        }
        if (lane < 4) {
            int k = kb*32 + k16*16 + 2*lane;
            g_context[b*H + k    ] = c0;
            g_context[b*H + k + 1] = c1;
            g_context[b*H + k + 8] = c2;
            g_context[b*H + k + 9] = c3;
        }
    }
}

// ---------------------------------------------------------------------------
__global__ void k_sim(const float* __restrict__ events,
                      const float* __restrict__ W_gate,
                      float* __restrict__ out)
{
    int b = blockIdx.x;
    int tid = threadIdx.x, warp = tid >> 5, lane = tid & 31;
    __shared__ float t[E];
    if (warp < E) {
        float acc = 0.f;
        for (int h = lane; h < H; h += 32)
            acc += g_context[b*H + h] * events[warp*H + h];
#pragma unroll
        for (int off = 16; off > 0; off >>= 1)
            acc += __shfl_down_sync(0xffffffffu, acc, off);
        if (lane == 0) t[warp] = acc;
    }
    __syncthreads();
    if (tid < E) {
        float s = 0.f;
#pragma unroll
        for (int e = 0; e < E; e++) s += t[e] * W_gate[tid*E + e];
        g_sim[b*E + tid] = s;
        out[OFF_S + b*E + tid] = s;
    }
}

// ---------------------------------------------------------------------------
__global__ void k_gates_init(const float* __restrict__ x,
                             const float* __restrict__ W_ih,
                             const float* __restrict__ b_ih,
                             const float* __restrict__ b_hh)
{
    int b = blockIdx.x;
    int j = blockIdx.y * 256 + threadIdx.x;
    const float* wr = W_ih + (size_t)j * LSTM_IN;
    float v = b_ih[j] + b_hh[j] + x[b] * wr[1034];
#pragma unroll
    for (int e = 0; e < E; e++) v += g_sim[b*E + e] * wr[1024 + e];
    g_gates[b*G4 + j] = v;
}

// ---------------------------------------------------------------------------
__global__ void k_lstm_final(const float* __restrict__ c0,
                             const float* __restrict__ ln_g,
                             const float* __restrict__ ln_b,
                             const float* __restrict__ W_fin,
                             const float* __restrict__ b_fin,
                             float* __restrict__ out)
{
    int b = blockIdx.x, tid = threadIdx.x;
    __shared__ float red[256];
    float hv[4];
    float sum = 0.f;
#pragma unroll
    for (int r = 0; r < 4; r++) {
        int h = r*256 + tid;
        float ig = g_gates[b*G4 + h];
        float fg = g_gates[b*G4 + 1024 + h];
        float gg = g_gates[b*G4 + 2048 + h];
        float og = g_gates[b*G4 + 3072 + h];
        float cn = sigmoidf_(fg) * c0[b*H + h] + sigmoidf_(ig) * tanhf(gg);
        float hn = sigmoidf_(og) * tanhf(cn);
        out[OFF_H + b*H + h] = hn;
        out[OFF_C + b*H + h] = cn;
        hv[r] = hn;
        sum += hn;
    }
    red[tid] = sum; __syncthreads();
    for (int off = 128; off > 0; off >>= 1) {
        if (tid < off) red[tid] += red[tid + off];
        __syncthreads();
    }
    float mu = red[0] * (1.f / H);
    __syncthreads();
    float sq = 0.f;
#pragma unroll
    for (int r = 0; r < 4; r++) { float d = hv[r] - mu; sq += d * d; }
    red[tid] = sq; __syncthreads();
    for (int off = 128; off > 0; off >>= 1) {
        if (tid < off) red[tid] += red[tid + off];
        __syncthreads();
    }
    float rstd = rsqrtf(red[0] * (1.f / H) + 1e-5f);
    __syncthreads();
    float fp = 0.f;
#pragma unroll
    for (int r = 0; r < 4; r++) {
        int h = r*256 + tid;
        float y = (hv[r] - mu) * rstd * ln_g[h] + ln_b[h];
        fp += y * W_fin[h];
    }
    red[tid] = fp; __syncthreads();
    for (int off = 128; off > 0; off >>= 1) {
        if (tid < off) red[tid] += red[tid + off];
        __syncthreads();
    }
    if (tid == 0) out[OFF_FIN + b] = red[0] + b_fin[0];
}

// ---------------------------------------------------------------------------
extern "C" void kernel_launch(void* const* d_in, const int* in_sizes, int n_in,
                              void* d_out, int out_size)
{
    const float* x      = (const float*)d_in[0];
    const float* h0     = (const float*)d_in[1];
    const float* c0     = (const float*)d_in[2];
    const float* enc    = (const float*)d_in[3];
    const float* W_enc  = (const float*)d_in[4];
    const float* W_dec  = (const float*)d_in[5];
    const float* w_val  = (const float*)d_in[6];
    const float* W_gate = (const float*)d_in[7];
    const float* events = (const float*)d_in[8];
    const float* W_ih   = (const float*)d_in[9];
    const float* W_hh   = (const float*)d_in[10];
    const float* b_ih   = (const float*)d_in[11];
    const float* b_hh   = (const float*)d_in[12];
    const float* ln_g   = (const float*)d_in[13];
    const float* ln_b   = (const float*)d_in[14];
    const float* W_fin  = (const float*)d_in[15];
    const float* b_fin  = (const float*)d_in[16];
    float* out = (float*)d_out;

    void* p;
    cudaGetSymbolAddress(&p, g_dec_proj); float*  dec_proj = (float*)p;
    cudaGetSymbolAddress(&p, g_context);  float*  context  = (float*)p;
    cudaGetSymbolAddress(&p, g_gates);    float*  gates    = (float*)p;
    cudaGetSymbolAddress(&p, g_enc_h);    __half* ench     = (__half*)p;
    cudaGetSymbolAddress(&p, g_wenc_h);   __half* wench    = (__half*)p;

    cudaFuncSetAttribute(k_attn_f16, cudaFuncAttributeMaxDynamicSharedMemorySize, ATTN_SMEM);

    // launch 1: fragment-major enc mirror + zeroing
    k_prep1<<<B*S*H*2/16/256, 256>>>(enc);
    // launch 2: fragment-pair-major W_enc mirror
    k_cvt_w<<<H*H*2/16/256, 256>>>(W_enc);
    // launch 3: dec_proj = h0 @ W_dec^T (tf32, split-K)
    k_tc64<<<dim3(H / 128, 8), 256>>>(h0, W_dec, H, nullptr, nullptr, 0, dec_proj, H);
    // launch 4: fused scores (ncu profiles this one)
    k_attn_f16<<<dim3(H / BN, B * S / BM), 256, ATTN_SMEM>>>(ench, wench, w_val);

    k_softmax<<<B, 256>>>(out);
    k_ctx<<<B * 4, 256>>>(ench, out);
    k_sim<<<B, 320>>>(events, W_gate, out);
    k_gates_init<<<dim3(B, 16), 256>>>(x, W_ih, b_ih, b_hh);

    // gates += context @ W_ih[:, :1024]^T + h0 @ W_hh^T (split-K, 512 CTAs)
    k_tc64<<<dim3(G4 / 128, 16), 256>>>(context, W_ih, LSTM_IN, h0, W_hh, H, gates, G4);

    k_lstm_final<<<B, 256>>>(c0, ln_g, ln_b, W_fin, b_fin, out);
}